// round 1
// baseline (speedup 1.0000x reference)
#include <cuda_runtime.h>

// Problem constants
constexpr int SEQ   = 2048;   // W (sequence / cropsize)
constexpr int CH    = 1024;   // BINS
constexpr int NHEAD = 16;
constexpr int HDIM  = 64;     // CH / NHEAD

// ---------------------------------------------------------------------------
// Scratch (alloc-free: static __device__ globals)
// ---------------------------------------------------------------------------
__device__ float g_q0[SEQ * CH];
__device__ float g_k0[SEQ * CH];
__device__ float g_v0[SEQ * CH];
__device__ float g_qc[SEQ * CH];
__device__ float g_kc[SEQ * CH];
__device__ float g_vc[SEQ * CH];
__device__ float g_S[(long long)NHEAD * SEQ * SEQ];   // 256 MB scores/attn
__device__ float g_attn[SEQ * CH];

// ---------------------------------------------------------------------------
// Generic 64x64-tile SGEMM: Cout[M,N] = A[M,K] @ B[K,N]
// 256 threads, 4x4 per-thread microtile, k-major smem, float4 smem reads.
// Per-z batch strides allow per-head use (A@V).
// All dims used here are multiples of 64 (K multiple of 16): no bounds checks.
// ---------------------------------------------------------------------------
__global__ __launch_bounds__(256) void gemm64(
    const float* __restrict__ A, const float* __restrict__ B,
    float* __restrict__ Cout,
    int lda, int ldb, int ldc, int K,
    long long sA, long long sB, long long sC)
{
    __shared__ float As[16][64];
    __shared__ float Bs[16][64];
    A    += (long long)blockIdx.z * sA;
    B    += (long long)blockIdx.z * sB;
    Cout += (long long)blockIdx.z * sC;
    const int m0  = blockIdx.y * 64;
    const int n0  = blockIdx.x * 64;
    const int tid = threadIdx.x;
    const int tx  = tid & 15, ty = tid >> 4;
    float acc[4][4] = {};

    for (int k0 = 0; k0 < K; k0 += 16) {
        #pragma unroll
        for (int l = 0; l < 4; l++) {
            int e  = tid + l * 256;
            int r  = e >> 4, kk = e & 15;
            As[kk][r] = A[(long long)(m0 + r) * lda + (k0 + kk)];
            int kk2 = e >> 6, c2 = e & 63;
            Bs[kk2][c2] = B[(long long)(k0 + kk2) * ldb + (n0 + c2)];
        }
        __syncthreads();
        #pragma unroll
        for (int kk = 0; kk < 16; kk++) {
            float4 a4 = *(const float4*)&As[kk][ty * 4];
            float4 b4 = *(const float4*)&Bs[kk][tx * 4];
            float a[4] = {a4.x, a4.y, a4.z, a4.w};
            float b[4] = {b4.x, b4.y, b4.z, b4.w};
            #pragma unroll
            for (int i = 0; i < 4; i++)
                #pragma unroll
                for (int j = 0; j < 4; j++)
                    acc[i][j] += a[i] * b[j];
        }
        __syncthreads();
    }
    #pragma unroll
    for (int i = 0; i < 4; i++) {
        float4 v = make_float4(acc[i][0], acc[i][1], acc[i][2], acc[i][3]);
        *(float4*)&Cout[(long long)(m0 + ty * 4 + i) * ldc + n0 + tx * 4] = v;
    }
}

// ---------------------------------------------------------------------------
// Depthwise conv1d over the sequence dim, kernel 3, 'same' padding.
// y[w,c] = cw[c][0]*x[w-1,c] + cw[c][1]*x[w,c] + cw[c][2]*x[w+1,c]
// ---------------------------------------------------------------------------
__global__ __launch_bounds__(256) void dwconv(
    const float* __restrict__ X, const float* __restrict__ cw,
    float* __restrict__ Y)
{
    int idx = blockIdx.x * 256 + threadIdx.x;
    if (idx >= SEQ * CH) return;
    int c = idx & (CH - 1);
    int w = idx >> 10;
    float w0 = cw[c * 3 + 0], w1 = cw[c * 3 + 1], w2 = cw[c * 3 + 2];
    float acc = X[idx] * w1;
    if (w > 0)       acc += X[idx - CH] * w0;
    if (w < SEQ - 1) acc += X[idx + CH] * w2;
    Y[idx] = acc;
}

// ---------------------------------------------------------------------------
// Scores with relative-position term (the "skew" degenerates to a transpose):
//   S[h,i,j] = ( sum_d q[h,i,d]*k[h,j,d]  +  sum_d q[h,j,d]*er[d,i] ) / 32
// Two fused GEMM terms per tile, same k-loop. 64x64 output tile, d-chunks of 16.
// ---------------------------------------------------------------------------
__global__ __launch_bounds__(256) void score64(
    const float* __restrict__ Qc, const float* __restrict__ Kc,
    const float* __restrict__ er, float* __restrict__ S)
{
    const int h  = blockIdx.z;
    const int i0 = blockIdx.y * 64;   // query rows (S rows)
    const int j0 = blockIdx.x * 64;   // key cols  (S cols)
    __shared__ float Qi[16][64], Kj[16][64], Qj[16][64], Es[16][64];
    const int tid = threadIdx.x;
    const int tx  = tid & 15, ty = tid >> 4;
    const int cb  = h * HDIM;
    float acc[4][4] = {};

    for (int d0 = 0; d0 < HDIM; d0 += 16) {
        #pragma unroll
        for (int l = 0; l < 4; l++) {
            int e = tid + l * 256;
            int r = e >> 4, kk = e & 15;
            Qi[kk][r] = Qc[(i0 + r) * CH + cb + d0 + kk];
            Qj[kk][r] = Qc[(j0 + r) * CH + cb + d0 + kk];
            Kj[kk][r] = Kc[(j0 + r) * CH + cb + d0 + kk];
            int kk2 = e >> 6, c2 = e & 63;
            Es[kk2][c2] = er[(d0 + kk2) * SEQ + i0 + c2];
        }
        __syncthreads();
        #pragma unroll
        for (int kk = 0; kk < 16; kk++) {
            float4 qi = *(const float4*)&Qi[kk][ty * 4];
            float4 es = *(const float4*)&Es[kk][ty * 4];
            float4 kj = *(const float4*)&Kj[kk][tx * 4];
            float4 qj = *(const float4*)&Qj[kk][tx * 4];
            float ai[4] = {qi.x, qi.y, qi.z, qi.w};
            float ei[4] = {es.x, es.y, es.z, es.w};
            float bj[4] = {kj.x, kj.y, kj.z, kj.w};
            float gj[4] = {qj.x, qj.y, qj.z, qj.w};
            #pragma unroll
            for (int i = 0; i < 4; i++)
                #pragma unroll
                for (int j = 0; j < 4; j++)
                    acc[i][j] += ai[i] * bj[j] + ei[i] * gj[j];
        }
        __syncthreads();
    }
    float* Srow = S + ((long long)h * SEQ + i0) * SEQ + j0;
    const float sc = 0.03125f;   // 1/sqrt(1024)
    #pragma unroll
    for (int i = 0; i < 4; i++) {
        float4 v = make_float4(acc[i][0] * sc, acc[i][1] * sc,
                               acc[i][2] * sc, acc[i][3] * sc);
        *(float4*)&Srow[(long long)(ty * 4 + i) * SEQ + tx * 4] = v;
    }
}

// ---------------------------------------------------------------------------
// Row softmax over the last dim (2048). One block per (row, head).
// ---------------------------------------------------------------------------
__global__ __launch_bounds__(256) void softmax_rows(float* __restrict__ S)
{
    float* row = S + ((long long)blockIdx.y * SEQ + blockIdx.x) * SEQ;
    __shared__ float red[256];
    const int tid = threadIdx.x;

    float m = -1e30f;
    for (int j = tid; j < SEQ; j += 256) m = fmaxf(m, row[j]);
    red[tid] = m; __syncthreads();
    for (int s = 128; s > 0; s >>= 1) {
        if (tid < s) red[tid] = fmaxf(red[tid], red[tid + s]);
        __syncthreads();
    }
    m = red[0]; __syncthreads();

    float sum = 0.f;
    for (int j = tid; j < SEQ; j += 256) {
        float e = __expf(row[j] - m);
        row[j] = e;
        sum += e;
    }
    red[tid] = sum; __syncthreads();
    for (int s = 128; s > 0; s >>= 1) {
        if (tid < s) red[tid] += red[tid + s];
        __syncthreads();
    }
    float inv = 1.0f / red[0];
    for (int j = tid; j < SEQ; j += 256) row[j] *= inv;
}

// ---------------------------------------------------------------------------
// Launch
// ---------------------------------------------------------------------------
extern "C" void kernel_launch(void* const* d_in, const int* in_sizes, int n_in,
                              void* d_out, int out_size)
{
    const float* x  = (const float*)d_in[0];
    const float* wq = (const float*)d_in[1];
    const float* wk = (const float*)d_in[2];
    const float* wv = (const float*)d_in[3];
    const float* wo = (const float*)d_in[4];
    const float* cw = (const float*)d_in[5];
    const float* er = (const float*)d_in[6];
    float* out = (float*)d_out;

    float *q0, *k0, *v0, *qc, *kc, *vc, *S, *attn;
    cudaGetSymbolAddress((void**)&q0,   g_q0);
    cudaGetSymbolAddress((void**)&k0,   g_k0);
    cudaGetSymbolAddress((void**)&v0,   g_v0);
    cudaGetSymbolAddress((void**)&qc,   g_qc);
    cudaGetSymbolAddress((void**)&kc,   g_kc);
    cudaGetSymbolAddress((void**)&vc,   g_vc);
    cudaGetSymbolAddress((void**)&S,    g_S);
    cudaGetSymbolAddress((void**)&attn, g_attn);

    dim3 blk(256);
    dim3 gLin(CH / 64, SEQ / 64, 1);

    // q/k/v projections
    gemm64<<<gLin, blk>>>(x, wq, q0, CH, CH, CH, CH, 0, 0, 0);
    gemm64<<<gLin, blk>>>(x, wk, k0, CH, CH, CH, CH, 0, 0, 0);
    gemm64<<<gLin, blk>>>(x, wv, v0, CH, CH, CH, CH, 0, 0, 0);

    // depthwise conv (reference applies q_conv to q, k AND v)
    int total = SEQ * CH;
    dwconv<<<(total + 255) / 256, blk>>>(q0, cw, qc);
    dwconv<<<(total + 255) / 256, blk>>>(k0, cw, kc);
    dwconv<<<(total + 255) / 256, blk>>>(v0, cw, vc);

    // scores (+ relative-position term), softmax
    score64<<<dim3(SEQ / 64, SEQ / 64, NHEAD), blk>>>(qc, kc, er, S);
    softmax_rows<<<dim3(SEQ, NHEAD), blk>>>(S);

    // A @ V  (per head: M=2048, N=64, K=2048)
    gemm64<<<dim3(1, SEQ / 64, NHEAD), blk>>>(S, vc, attn,
                                              SEQ, CH, CH, SEQ,
                                              (long long)SEQ * SEQ, 64, 64);

    // output projection
    gemm64<<<gLin, blk>>>(attn, wo, out, CH, CH, CH, CH, 0, 0, 0);
}

// round 2
// speedup vs baseline: 2.3058x; 2.3058x over previous
#include <cuda_runtime.h>

constexpr int SEQ   = 2048;
constexpr int CH    = 1024;
constexpr int NHEAD = 16;
constexpr int HDIM  = 64;

// ---------------------------------------------------------------------------
// Scratch
// ---------------------------------------------------------------------------
__device__ float g_q0[SEQ * CH];
__device__ float g_k0[SEQ * CH];
__device__ float g_v0[SEQ * CH];
__device__ float g_qc[SEQ * CH];
__device__ float g_kc[SEQ * CH];
__device__ float g_vc[SEQ * CH];
__device__ float g_S[(long long)NHEAD * SEQ * SEQ];
__device__ float g_attn[SEQ * CH];

// ---------------------------------------------------------------------------
// TF32 helpers
// ---------------------------------------------------------------------------
__device__ __forceinline__ void split_tf32(float x, unsigned& hi, unsigned& lo) {
    asm("cvt.rna.tf32.f32 %0, %1;" : "=r"(hi) : "f"(x));
    float r = x - __uint_as_float(hi);
    asm("cvt.rna.tf32.f32 %0, %1;" : "=r"(lo) : "f"(r));
}

__device__ __forceinline__ void mma_tf32(float* c, const unsigned* a, const unsigned* b) {
    asm volatile(
        "mma.sync.aligned.m16n8k8.row.col.f32.tf32.tf32.f32 "
        "{%0,%1,%2,%3},{%4,%5,%6,%7},{%8,%9},{%0,%1,%2,%3};"
        : "+f"(c[0]), "+f"(c[1]), "+f"(c[2]), "+f"(c[3])
        : "r"(a[0]), "r"(a[1]), "r"(a[2]), "r"(a[3]), "r"(b[0]), "r"(b[1]));
}

// ---------------------------------------------------------------------------
// Generic TF32x3 GEMM: C[M,N] = alpha * A[M,K] @ B[K,N]
// A row-major, B row-major (loaded transposed into [n][k] smem).
// 256 threads. Smem stride 20 words -> conflict-free fragment loads.
// ---------------------------------------------------------------------------
template<int BM, int BN, int WM, int WN>
__global__ __launch_bounds__(256) void mma_gemm(
    const float* __restrict__ A, const float* __restrict__ B, float* __restrict__ C,
    int lda, int ldb, int ldc, int K, float alpha,
    long long sA, long long sB, long long sC)
{
    constexpr int WARPS_M = BM / WM;
    constexpr int WARPS_N = BN / WN;
    static_assert(WARPS_M * WARPS_N == 8, "");
    constexpr int MT = WM / 16, NT = WN / 8;
    constexpr int LDS_ = 20;

    __shared__ unsigned Ah[BM * LDS_], Al[BM * LDS_];
    __shared__ unsigned Bh[BN * LDS_], Bl[BN * LDS_];

    A += (long long)blockIdx.z * sA;
    B += (long long)blockIdx.z * sB;
    C += (long long)blockIdx.z * sC;

    const int m0 = blockIdx.y * BM, n0 = blockIdx.x * BN;
    const int tid = threadIdx.x, wid = tid >> 5, lane = tid & 31;
    const int gid = lane >> 2, tig = lane & 3;
    const int wm0 = (wid % WARPS_M) * WM, wn0 = (wid / WARPS_M) * WN;

    float acc[MT][NT][4];
    #pragma unroll
    for (int i = 0; i < MT; i++)
        #pragma unroll
        for (int j = 0; j < NT; j++)
            #pragma unroll
            for (int r = 0; r < 4; r++) acc[i][j][r] = 0.f;

    for (int k0 = 0; k0 < K; k0 += 16) {
        // A tile: BM x 16, row reads (float4 along k)
        #pragma unroll
        for (int i = 0; i < BM * 4 / 256; i++) {
            int idx = tid + i * 256;
            int m = idx >> 2, kq = (idx & 3) * 4;
            float4 v = *(const float4*)(A + (long long)(m0 + m) * lda + k0 + kq);
            float f[4] = {v.x, v.y, v.z, v.w};
            #pragma unroll
            for (int j = 0; j < 4; j++) {
                unsigned h, l; split_tf32(f[j], h, l);
                Ah[m * LDS_ + kq + j] = h;
                Al[m * LDS_ + kq + j] = l;
            }
        }
        // B tile: 16 x BN, transposed into [n][k]
        #pragma unroll
        for (int i = 0; i < BN * 4 / 256; i++) {
            int idx = tid + i * 256;
            int n4 = idx % (BN / 4), kk = idx / (BN / 4);
            float4 v = *(const float4*)(B + (long long)(k0 + kk) * ldb + n0 + n4 * 4);
            float f[4] = {v.x, v.y, v.z, v.w};
            #pragma unroll
            for (int j = 0; j < 4; j++) {
                unsigned h, l; split_tf32(f[j], h, l);
                Bh[(n4 * 4 + j) * LDS_ + kk] = h;
                Bl[(n4 * 4 + j) * LDS_ + kk] = l;
            }
        }
        __syncthreads();

        #pragma unroll
        for (int ks = 0; ks < 16; ks += 8) {
            unsigned ah[MT][4], al[MT][4], bh[NT][2], bl[NT][2];
            #pragma unroll
            for (int mt = 0; mt < MT; mt++) {
                int base = (wm0 + mt * 16 + gid) * LDS_ + ks + tig;
                ah[mt][0] = Ah[base];            al[mt][0] = Al[base];
                ah[mt][1] = Ah[base + 8 * LDS_]; al[mt][1] = Al[base + 8 * LDS_];
                ah[mt][2] = Ah[base + 4];        al[mt][2] = Al[base + 4];
                ah[mt][3] = Ah[base + 8 * LDS_ + 4]; al[mt][3] = Al[base + 8 * LDS_ + 4];
            }
            #pragma unroll
            for (int nt = 0; nt < NT; nt++) {
                int base = (wn0 + nt * 8 + gid) * LDS_ + ks + tig;
                bh[nt][0] = Bh[base];     bl[nt][0] = Bl[base];
                bh[nt][1] = Bh[base + 4]; bl[nt][1] = Bl[base + 4];
            }
            #pragma unroll
            for (int mt = 0; mt < MT; mt++)
                #pragma unroll
                for (int nt = 0; nt < NT; nt++) {
                    mma_tf32(acc[mt][nt], ah[mt], bh[nt]);
                    mma_tf32(acc[mt][nt], ah[mt], bl[nt]);
                    mma_tf32(acc[mt][nt], al[mt], bh[nt]);
                }
        }
        __syncthreads();
    }

    #pragma unroll
    for (int mt = 0; mt < MT; mt++)
        #pragma unroll
        for (int nt = 0; nt < NT; nt++) {
            int r = m0 + wm0 + mt * 16 + gid;
            int c = n0 + wn0 + nt * 8 + 2 * tig;
            float2 v0 = make_float2(alpha * acc[mt][nt][0], alpha * acc[mt][nt][1]);
            float2 v1 = make_float2(alpha * acc[mt][nt][2], alpha * acc[mt][nt][3]);
            *(float2*)(C + (long long)r * ldc + c) = v0;
            *(float2*)(C + (long long)(r + 8) * ldc + c) = v1;
        }
}

// ---------------------------------------------------------------------------
// Score kernel (TF32x3):
//   S[h,i,j] = ( q_i . k_j  +  erT_i . q_j ) / 32
// pass 0: A = Qc rows(i), B = Kc rows(j)    [both natural row reads]
// pass 1: A = er transposed (erT[i][d]), B = Qc rows(j)
// ---------------------------------------------------------------------------
__global__ __launch_bounds__(256) void score_mma(
    const float* __restrict__ Qc, const float* __restrict__ Kc,
    const float* __restrict__ er, float* __restrict__ S)
{
    constexpr int BM = 128, WM = 64, WN = 32;
    constexpr int WARPS_M = 2;
    constexpr int MT = WM / 16, NT = WN / 8;
    constexpr int LDS_ = 20;

    __shared__ unsigned Ah[BM * LDS_], Al[BM * LDS_];
    __shared__ unsigned Bh[BM * LDS_], Bl[BM * LDS_];

    const int h = blockIdx.z;
    const int i0 = blockIdx.y * 128, j0 = blockIdx.x * 128;
    const int cb = h * HDIM;
    const int tid = threadIdx.x, wid = tid >> 5, lane = tid & 31;
    const int gid = lane >> 2, tig = lane & 3;
    const int wm0 = (wid % WARPS_M) * WM, wn0 = (wid / WARPS_M) * WN;

    float acc[MT][NT][4];
    #pragma unroll
    for (int i = 0; i < MT; i++)
        #pragma unroll
        for (int j = 0; j < NT; j++)
            #pragma unroll
            for (int r = 0; r < 4; r++) acc[i][j][r] = 0.f;

    for (int pass = 0; pass < 2; pass++) {
        const float* Bsrc = pass ? Qc : Kc;
        for (int d0 = 0; d0 < HDIM; d0 += 16) {
            if (pass == 0) {
                #pragma unroll
                for (int i = 0; i < 2; i++) {
                    int idx = tid + i * 256;
                    int m = idx >> 2, kq = (idx & 3) * 4;
                    float4 v = *(const float4*)(Qc + (long long)(i0 + m) * CH + cb + d0 + kq);
                    float f[4] = {v.x, v.y, v.z, v.w};
                    #pragma unroll
                    for (int j = 0; j < 4; j++) {
                        unsigned hh, ll; split_tf32(f[j], hh, ll);
                        Ah[m * LDS_ + kq + j] = hh;
                        Al[m * LDS_ + kq + j] = ll;
                    }
                }
            } else {
                // erT tile: A[m=i][k=d] = er[d][i], transposed load
                #pragma unroll
                for (int i = 0; i < 2; i++) {
                    int idx = tid + i * 256;
                    int i4 = idx % 32, kk = idx / 32;
                    float4 v = *(const float4*)(er + (long long)(d0 + kk) * SEQ + i0 + i4 * 4);
                    float f[4] = {v.x, v.y, v.z, v.w};
                    #pragma unroll
                    for (int j = 0; j < 4; j++) {
                        unsigned hh, ll; split_tf32(f[j], hh, ll);
                        Ah[(i4 * 4 + j) * LDS_ + kk] = hh;
                        Al[(i4 * 4 + j) * LDS_ + kk] = ll;
                    }
                }
            }
            // B tile: rows (j0..j0+127) of Kc (pass0) / Qc (pass1), [n][k] natural
            #pragma unroll
            for (int i = 0; i < 2; i++) {
                int idx = tid + i * 256;
                int n = idx >> 2, kq = (idx & 3) * 4;
                float4 v = *(const float4*)(Bsrc + (long long)(j0 + n) * CH + cb + d0 + kq);
                float f[4] = {v.x, v.y, v.z, v.w};
                #pragma unroll
                for (int j = 0; j < 4; j++) {
                    unsigned hh, ll; split_tf32(f[j], hh, ll);
                    Bh[n * LDS_ + kq + j] = hh;
                    Bl[n * LDS_ + kq + j] = ll;
                }
            }
            __syncthreads();

            #pragma unroll
            for (int ks = 0; ks < 16; ks += 8) {
                unsigned ah[MT][4], al[MT][4], bh[NT][2], bl[NT][2];
                #pragma unroll
                for (int mt = 0; mt < MT; mt++) {
                    int base = (wm0 + mt * 16 + gid) * LDS_ + ks + tig;
                    ah[mt][0] = Ah[base];            al[mt][0] = Al[base];
                    ah[mt][1] = Ah[base + 8 * LDS_]; al[mt][1] = Al[base + 8 * LDS_];
                    ah[mt][2] = Ah[base + 4];        al[mt][2] = Al[base + 4];
                    ah[mt][3] = Ah[base + 8 * LDS_ + 4]; al[mt][3] = Al[base + 8 * LDS_ + 4];
                }
                #pragma unroll
                for (int nt = 0; nt < NT; nt++) {
                    int base = (wn0 + nt * 8 + gid) * LDS_ + ks + tig;
                    bh[nt][0] = Bh[base];     bl[nt][0] = Bl[base];
                    bh[nt][1] = Bh[base + 4]; bl[nt][1] = Bl[base + 4];
                }
                #pragma unroll
                for (int mt = 0; mt < MT; mt++)
                    #pragma unroll
                    for (int nt = 0; nt < NT; nt++) {
                        mma_tf32(acc[mt][nt], ah[mt], bh[nt]);
                        mma_tf32(acc[mt][nt], ah[mt], bl[nt]);
                        mma_tf32(acc[mt][nt], al[mt], bh[nt]);
                    }
            }
            __syncthreads();
        }
    }

    const float sc = 0.03125f;  // 1/sqrt(1024)
    float* Sh = g_S; (void)Sh;
    #pragma unroll
    for (int mt = 0; mt < MT; mt++)
        #pragma unroll
        for (int nt = 0; nt < NT; nt++) {
            int r = i0 + wm0 + mt * 16 + gid;
            int c = j0 + wn0 + nt * 8 + 2 * tig;
            float2 v0 = make_float2(sc * acc[mt][nt][0], sc * acc[mt][nt][1]);
            float2 v1 = make_float2(sc * acc[mt][nt][2], sc * acc[mt][nt][3]);
            *(float2*)(S + ((long long)h * SEQ + r) * SEQ + c) = v0;
            *(float2*)(S + ((long long)h * SEQ + r + 8) * SEQ + c) = v1;
        }
}

// ---------------------------------------------------------------------------
// Depthwise conv1d, k=3, same padding
// ---------------------------------------------------------------------------
__global__ __launch_bounds__(256) void dwconv(
    const float* __restrict__ X, const float* __restrict__ cw,
    float* __restrict__ Y)
{
    int idx = blockIdx.x * 256 + threadIdx.x;
    if (idx >= SEQ * CH) return;
    int c = idx & (CH - 1);
    int w = idx >> 10;
    float w0 = cw[c * 3 + 0], w1 = cw[c * 3 + 1], w2 = cw[c * 3 + 2];
    float acc = X[idx] * w1;
    if (w > 0)       acc += X[idx - CH] * w0;
    if (w < SEQ - 1) acc += X[idx + CH] * w2;
    Y[idx] = acc;
}

// ---------------------------------------------------------------------------
// Register-resident row softmax (row = 2048 floats, 256 threads, 8 each)
// ---------------------------------------------------------------------------
__global__ __launch_bounds__(256) void softmax_rows(float* __restrict__ S)
{
    float* row = S + ((long long)blockIdx.y * SEQ + blockIdx.x) * SEQ;
    const int tid = threadIdx.x;
    __shared__ float red[8];

    float4 v[2];
    v[0] = ((float4*)row)[tid];
    v[1] = ((float4*)row)[tid + 256];

    float m = fmaxf(fmaxf(fmaxf(v[0].x, v[0].y), fmaxf(v[0].z, v[0].w)),
                    fmaxf(fmaxf(v[1].x, v[1].y), fmaxf(v[1].z, v[1].w)));
    #pragma unroll
    for (int s = 16; s > 0; s >>= 1) m = fmaxf(m, __shfl_xor_sync(~0u, m, s));
    if ((tid & 31) == 0) red[tid >> 5] = m;
    __syncthreads();
    m = red[0];
    #pragma unroll
    for (int i = 1; i < 8; i++) m = fmaxf(m, red[i]);
    __syncthreads();

    float sum = 0.f;
    #pragma unroll
    for (int i = 0; i < 2; i++) {
        v[i].x = __expf(v[i].x - m); sum += v[i].x;
        v[i].y = __expf(v[i].y - m); sum += v[i].y;
        v[i].z = __expf(v[i].z - m); sum += v[i].z;
        v[i].w = __expf(v[i].w - m); sum += v[i].w;
    }
    #pragma unroll
    for (int s = 16; s > 0; s >>= 1) sum += __shfl_xor_sync(~0u, sum, s);
    if ((tid & 31) == 0) red[tid >> 5] = sum;
    __syncthreads();
    sum = 0.f;
    #pragma unroll
    for (int i = 0; i < 8; i++) sum += red[i];
    float inv = 1.0f / sum;

    #pragma unroll
    for (int i = 0; i < 2; i++) {
        v[i].x *= inv; v[i].y *= inv; v[i].z *= inv; v[i].w *= inv;
    }
    ((float4*)row)[tid] = v[0];
    ((float4*)row)[tid + 256] = v[1];
}

// ---------------------------------------------------------------------------
// Launch
// ---------------------------------------------------------------------------
extern "C" void kernel_launch(void* const* d_in, const int* in_sizes, int n_in,
                              void* d_out, int out_size)
{
    const float* x  = (const float*)d_in[0];
    const float* wq = (const float*)d_in[1];
    const float* wk = (const float*)d_in[2];
    const float* wv = (const float*)d_in[3];
    const float* wo = (const float*)d_in[4];
    const float* cw = (const float*)d_in[5];
    const float* er = (const float*)d_in[6];
    float* out = (float*)d_out;

    float *q0, *k0, *v0, *qc, *kc, *vc, *S, *attn;
    cudaGetSymbolAddress((void**)&q0,   g_q0);
    cudaGetSymbolAddress((void**)&k0,   g_k0);
    cudaGetSymbolAddress((void**)&v0,   g_v0);
    cudaGetSymbolAddress((void**)&qc,   g_qc);
    cudaGetSymbolAddress((void**)&kc,   g_kc);
    cudaGetSymbolAddress((void**)&vc,   g_vc);
    cudaGetSymbolAddress((void**)&S,    g_S);
    cudaGetSymbolAddress((void**)&attn, g_attn);

    dim3 blk(256);
    dim3 gProj(CH / 128, SEQ / 128, 1);   // (8, 16)

    // q/k/v projections  (TF32x3 MMA)
    mma_gemm<128,128,64,32><<<gProj, blk>>>(x, wq, q0, CH, CH, CH, CH, 1.f, 0, 0, 0);
    mma_gemm<128,128,64,32><<<gProj, blk>>>(x, wk, k0, CH, CH, CH, CH, 1.f, 0, 0, 0);
    mma_gemm<128,128,64,32><<<gProj, blk>>>(x, wv, v0, CH, CH, CH, CH, 1.f, 0, 0, 0);

    // depthwise conv (reference applies q_conv to q, k AND v)
    int total = SEQ * CH;
    dwconv<<<(total + 255) / 256, blk>>>(q0, cw, qc);
    dwconv<<<(total + 255) / 256, blk>>>(k0, cw, kc);
    dwconv<<<(total + 255) / 256, blk>>>(v0, cw, vc);

    // scores (+ relative-position term), softmax
    score_mma<<<dim3(SEQ / 128, SEQ / 128, NHEAD), blk>>>(qc, kc, er, S);
    softmax_rows<<<dim3(SEQ, NHEAD), blk>>>(S);

    // A @ V  per head: M=2048, N=64, K=2048
    mma_gemm<128,64,32,32><<<dim3(1, SEQ / 128, NHEAD), blk>>>(
        S, vc, attn, SEQ, CH, CH, SEQ, 1.f,
        (long long)SEQ * SEQ, 64, 64);

    // output projection
    mma_gemm<128,128,64,32><<<gProj, blk>>>(attn, wo, out, CH, CH, CH, CH, 1.f, 0, 0, 0);
}

// round 3
// speedup vs baseline: 2.3383x; 1.0141x over previous
#include <cuda_runtime.h>

constexpr int SEQ   = 2048;
constexpr int CH    = 1024;
constexpr int NHEAD = 16;
constexpr int HDIM  = 64;

// ---------------------------------------------------------------------------
// Scratch
// ---------------------------------------------------------------------------
__device__ float g_q0[SEQ * CH];
__device__ float g_k0[SEQ * CH];
__device__ float g_v0[SEQ * CH];
__device__ float g_qc[SEQ * CH];
__device__ float g_kc[SEQ * CH];
__device__ float g_vc[SEQ * CH];
__device__ float g_S[(long long)NHEAD * SEQ * SEQ];
__device__ float g_attn[SEQ * CH];

// ---------------------------------------------------------------------------
// TF32 helpers
// ---------------------------------------------------------------------------
__device__ __forceinline__ void split_tf32(float x, unsigned& hi, unsigned& lo) {
    asm("cvt.rna.tf32.f32 %0, %1;" : "=r"(hi) : "f"(x));
    float r = x - __uint_as_float(hi);
    asm("cvt.rna.tf32.f32 %0, %1;" : "=r"(lo) : "f"(r));
}

__device__ __forceinline__ void mma_tf32(float* c, const unsigned* a, const unsigned* b) {
    asm volatile(
        "mma.sync.aligned.m16n8k8.row.col.f32.tf32.tf32.f32 "
        "{%0,%1,%2,%3},{%4,%5,%6,%7},{%8,%9},{%0,%1,%2,%3};"
        : "+f"(c[0]), "+f"(c[1]), "+f"(c[2]), "+f"(c[3])
        : "r"(a[0]), "r"(a[1]), "r"(a[2]), "r"(a[3]), "r"(b[0]), "r"(b[1]));
}

// ---------------------------------------------------------------------------
// Shared TF32x3 GEMM body: C[M,N] = alpha * A[M,K] @ B[K,N]
// A row-major, B row-major (transposed into [n][k] smem).
// 256 threads, register-prefetch double buffering of global loads.
// ---------------------------------------------------------------------------
template<int BM, int BN, int WM, int WN>
__device__ __forceinline__ void gemm_body(
    const float* __restrict__ A, const float* __restrict__ B, float* __restrict__ C,
    int lda, int ldb, int ldc, int K, float alpha)
{
    constexpr int WARPS_M = BM / WM;
    constexpr int WARPS_N = BN / WN;
    static_assert(WARPS_M * WARPS_N == 8, "");
    constexpr int MT = WM / 16, NT = WN / 8;
    constexpr int LDS_ = 20;
    constexpr int NA = BM / 64;   // float4 loads per thread for A tile (BM x 16)
    constexpr int NB = BN / 64;   // float4 loads per thread for B tile (16 x BN)

    __shared__ unsigned Ah[BM * LDS_], Al[BM * LDS_];
    __shared__ unsigned Bh[BN * LDS_], Bl[BN * LDS_];

    const int m0 = blockIdx.y * BM, n0 = blockIdx.x * BN;
    const int tid = threadIdx.x, wid = tid >> 5, lane = tid & 31;
    const int gid = lane >> 2, tig = lane & 3;
    const int wm0 = (wid % WARPS_M) * WM, wn0 = (wid / WARPS_M) * WN;

    float acc[MT][NT][4];
    #pragma unroll
    for (int i = 0; i < MT; i++)
        #pragma unroll
        for (int j = 0; j < NT; j++)
            #pragma unroll
            for (int r = 0; r < 4; r++) acc[i][j][r] = 0.f;

    float4 pa[NA], pb[NB];

    // prefetch k0 = 0
    #pragma unroll
    for (int i = 0; i < NA; i++) {
        int idx = tid + i * 256;
        int m = idx >> 2, kq = (idx & 3) * 4;
        pa[i] = *(const float4*)(A + (long long)(m0 + m) * lda + kq);
    }
    #pragma unroll
    for (int i = 0; i < NB; i++) {
        int idx = tid + i * 256;
        int n4 = idx % (BN / 4), kk = idx / (BN / 4);
        pb[i] = *(const float4*)(B + (long long)kk * ldb + n0 + n4 * 4);
    }

    for (int k0 = 0; k0 < K; k0 += 16) {
        // store current tile (split to tf32 hi/lo)
        #pragma unroll
        for (int i = 0; i < NA; i++) {
            int idx = tid + i * 256;
            int m = idx >> 2, kq = (idx & 3) * 4;
            float f[4] = {pa[i].x, pa[i].y, pa[i].z, pa[i].w};
            #pragma unroll
            for (int j = 0; j < 4; j++) {
                unsigned h, l; split_tf32(f[j], h, l);
                Ah[m * LDS_ + kq + j] = h;
                Al[m * LDS_ + kq + j] = l;
            }
        }
        #pragma unroll
        for (int i = 0; i < NB; i++) {
            int idx = tid + i * 256;
            int n4 = idx % (BN / 4), kk = idx / (BN / 4);
            float f[4] = {pb[i].x, pb[i].y, pb[i].z, pb[i].w};
            #pragma unroll
            for (int j = 0; j < 4; j++) {
                unsigned h, l; split_tf32(f[j], h, l);
                Bh[(n4 * 4 + j) * LDS_ + kk] = h;
                Bl[(n4 * 4 + j) * LDS_ + kk] = l;
            }
        }
        __syncthreads();

        // prefetch next tile (latency hidden by MMA loop below)
        if (k0 + 16 < K) {
            #pragma unroll
            for (int i = 0; i < NA; i++) {
                int idx = tid + i * 256;
                int m = idx >> 2, kq = (idx & 3) * 4;
                pa[i] = *(const float4*)(A + (long long)(m0 + m) * lda + k0 + 16 + kq);
            }
            #pragma unroll
            for (int i = 0; i < NB; i++) {
                int idx = tid + i * 256;
                int n4 = idx % (BN / 4), kk = idx / (BN / 4);
                pb[i] = *(const float4*)(B + (long long)(k0 + 16 + kk) * ldb + n0 + n4 * 4);
            }
        }

        #pragma unroll
        for (int ks = 0; ks < 16; ks += 8) {
            unsigned ah[MT][4], al[MT][4], bh[NT][2], bl[NT][2];
            #pragma unroll
            for (int mt = 0; mt < MT; mt++) {
                int base = (wm0 + mt * 16 + gid) * LDS_ + ks + tig;
                ah[mt][0] = Ah[base];            al[mt][0] = Al[base];
                ah[mt][1] = Ah[base + 8 * LDS_]; al[mt][1] = Al[base + 8 * LDS_];
                ah[mt][2] = Ah[base + 4];        al[mt][2] = Al[base + 4];
                ah[mt][3] = Ah[base + 8 * LDS_ + 4]; al[mt][3] = Al[base + 8 * LDS_ + 4];
            }
            #pragma unroll
            for (int nt = 0; nt < NT; nt++) {
                int base = (wn0 + nt * 8 + gid) * LDS_ + ks + tig;
                bh[nt][0] = Bh[base];     bl[nt][0] = Bl[base];
                bh[nt][1] = Bh[base + 4]; bl[nt][1] = Bl[base + 4];
            }
            #pragma unroll
            for (int mt = 0; mt < MT; mt++)
                #pragma unroll
                for (int nt = 0; nt < NT; nt++) {
                    mma_tf32(acc[mt][nt], ah[mt], bh[nt]);
                    mma_tf32(acc[mt][nt], ah[mt], bl[nt]);
                    mma_tf32(acc[mt][nt], al[mt], bh[nt]);
                }
        }
        __syncthreads();
    }

    #pragma unroll
    for (int mt = 0; mt < MT; mt++)
        #pragma unroll
        for (int nt = 0; nt < NT; nt++) {
            int r = m0 + wm0 + mt * 16 + gid;
            int c = n0 + wn0 + nt * 8 + 2 * tig;
            float2 v0 = make_float2(alpha * acc[mt][nt][0], alpha * acc[mt][nt][1]);
            float2 v1 = make_float2(alpha * acc[mt][nt][2], alpha * acc[mt][nt][3]);
            *(float2*)(C + (long long)r * ldc + c) = v0;
            *(float2*)(C + (long long)(r + 8) * ldc + c) = v1;
        }
}

// Fused Q/K/V projection: blockIdx.z selects the weight/output pair.
__global__ __launch_bounds__(256) void qkv_gemm(
    const float* __restrict__ x,
    const float* __restrict__ wq, const float* __restrict__ wk, const float* __restrict__ wv,
    float* __restrict__ q0, float* __restrict__ k0, float* __restrict__ v0)
{
    const int z = blockIdx.z;
    const float* W = (z == 0) ? wq : (z == 1) ? wk : wv;
    float*       O = (z == 0) ? q0 : (z == 1) ? k0 : v0;
    gemm_body<128,128,64,32>(x, W, O, CH, CH, CH, CH, 1.f);
}

// Generic (z-batched) GEMM.
__global__ __launch_bounds__(256) void batch_gemm_128(
    const float* __restrict__ A, const float* __restrict__ B, float* __restrict__ C,
    int lda, int ldb, int ldc, int K, float alpha,
    long long sA, long long sB, long long sC)
{
    gemm_body<128,128,64,32>(A + (long long)blockIdx.z * sA,
                             B + (long long)blockIdx.z * sB,
                             C + (long long)blockIdx.z * sC,
                             lda, ldb, ldc, K, alpha);
}

__global__ __launch_bounds__(256) void batch_gemm_av(
    const float* __restrict__ A, const float* __restrict__ B, float* __restrict__ C,
    int lda, int ldb, int ldc, int K, float alpha,
    long long sA, long long sB, long long sC)
{
    gemm_body<128,64,32,32>(A + (long long)blockIdx.z * sA,
                            B + (long long)blockIdx.z * sB,
                            C + (long long)blockIdx.z * sC,
                            lda, ldb, ldc, K, alpha);
}

// ---------------------------------------------------------------------------
// Score kernel (TF32x3):  S[h,i,j] = ( q_i . k_j  +  erT_i . q_j ) / 32
// Linearized 8 k-iterations (2 passes x 4 d-chunks), register prefetch.
// ---------------------------------------------------------------------------
__global__ __launch_bounds__(256) void score_mma(
    const float* __restrict__ Qc, const float* __restrict__ Kc,
    const float* __restrict__ er, float* __restrict__ S)
{
    constexpr int BM = 128, WM = 64, WN = 32;
    constexpr int WARPS_M = 2;
    constexpr int MT = WM / 16, NT = WN / 8;
    constexpr int LDS_ = 20;

    __shared__ unsigned Ah[BM * LDS_], Al[BM * LDS_];
    __shared__ unsigned Bh[BM * LDS_], Bl[BM * LDS_];

    const int h = blockIdx.z;
    const int i0 = blockIdx.y * 128, j0 = blockIdx.x * 128;
    const int cb = h * HDIM;
    const int tid = threadIdx.x, wid = tid >> 5, lane = tid & 31;
    const int gid = lane >> 2, tig = lane & 3;
    const int wm0 = (wid % WARPS_M) * WM, wn0 = (wid / WARPS_M) * WN;

    float acc[MT][NT][4];
    #pragma unroll
    for (int i = 0; i < MT; i++)
        #pragma unroll
        for (int j = 0; j < NT; j++)
            #pragma unroll
            for (int r = 0; r < 4; r++) acc[i][j][r] = 0.f;

    float4 pa[2], pb[2];
    bool a_trans_p = false;   // layout of pa: false = row-read, true = erT

    // iteration it in [0,8): pass = it>>2, d0 = (it&3)*16
    auto loadA = [&](int it) {
        int pass = it >> 2, d0 = (it & 3) * 16;
        if (pass == 0) {
            #pragma unroll
            for (int i = 0; i < 2; i++) {
                int idx = tid + i * 256;
                int m = idx >> 2, kq = (idx & 3) * 4;
                pa[i] = *(const float4*)(Qc + (long long)(i0 + m) * CH + cb + d0 + kq);
            }
            a_trans_p = false;
        } else {
            #pragma unroll
            for (int i = 0; i < 2; i++) {
                int idx = tid + i * 256;
                int i4 = idx % 32, kk = idx / 32;
                pa[i] = *(const float4*)(er + (long long)(d0 + kk) * SEQ + i0 + i4 * 4);
            }
            a_trans_p = true;
        }
    };
    auto loadB = [&](int it) {
        int pass = it >> 2, d0 = (it & 3) * 16;
        const float* Bsrc = pass ? Qc : Kc;
        #pragma unroll
        for (int i = 0; i < 2; i++) {
            int idx = tid + i * 256;
            int n = idx >> 2, kq = (idx & 3) * 4;
            pb[i] = *(const float4*)(Bsrc + (long long)(j0 + n) * CH + cb + d0 + kq);
        }
    };

    loadA(0); loadB(0);

    for (int it = 0; it < 8; it++) {
        // store current tiles
        bool at = a_trans_p;
        #pragma unroll
        for (int i = 0; i < 2; i++) {
            int idx = tid + i * 256;
            float f[4] = {pa[i].x, pa[i].y, pa[i].z, pa[i].w};
            if (!at) {
                int m = idx >> 2, kq = (idx & 3) * 4;
                #pragma unroll
                for (int j = 0; j < 4; j++) {
                    unsigned hh, ll; split_tf32(f[j], hh, ll);
                    Ah[m * LDS_ + kq + j] = hh;
                    Al[m * LDS_ + kq + j] = ll;
                }
            } else {
                int i4 = idx % 32, kk = idx / 32;
                #pragma unroll
                for (int j = 0; j < 4; j++) {
                    unsigned hh, ll; split_tf32(f[j], hh, ll);
                    Ah[(i4 * 4 + j) * LDS_ + kk] = hh;
                    Al[(i4 * 4 + j) * LDS_ + kk] = ll;
                }
            }
        }
        #pragma unroll
        for (int i = 0; i < 2; i++) {
            int idx = tid + i * 256;
            int n = idx >> 2, kq = (idx & 3) * 4;
            float f[4] = {pb[i].x, pb[i].y, pb[i].z, pb[i].w};
            #pragma unroll
            for (int j = 0; j < 4; j++) {
                unsigned hh, ll; split_tf32(f[j], hh, ll);
                Bh[n * LDS_ + kq + j] = hh;
                Bl[n * LDS_ + kq + j] = ll;
            }
        }
        __syncthreads();

        if (it + 1 < 8) { loadA(it + 1); loadB(it + 1); }

        #pragma unroll
        for (int ks = 0; ks < 16; ks += 8) {
            unsigned ah[MT][4], al[MT][4], bh[NT][2], bl[NT][2];
            #pragma unroll
            for (int mt = 0; mt < MT; mt++) {
                int base = (wm0 + mt * 16 + gid) * LDS_ + ks + tig;
                ah[mt][0] = Ah[base];            al[mt][0] = Al[base];
                ah[mt][1] = Ah[base + 8 * LDS_]; al[mt][1] = Al[base + 8 * LDS_];
                ah[mt][2] = Ah[base + 4];        al[mt][2] = Al[base + 4];
                ah[mt][3] = Ah[base + 8 * LDS_ + 4]; al[mt][3] = Al[base + 8 * LDS_ + 4];
            }
            #pragma unroll
            for (int nt = 0; nt < NT; nt++) {
                int base = (wn0 + nt * 8 + gid) * LDS_ + ks + tig;
                bh[nt][0] = Bh[base];     bl[nt][0] = Bl[base];
                bh[nt][1] = Bh[base + 4]; bl[nt][1] = Bl[base + 4];
            }
            #pragma unroll
            for (int mt = 0; mt < MT; mt++)
                #pragma unroll
                for (int nt = 0; nt < NT; nt++) {
                    mma_tf32(acc[mt][nt], ah[mt], bh[nt]);
                    mma_tf32(acc[mt][nt], ah[mt], bl[nt]);
                    mma_tf32(acc[mt][nt], al[mt], bh[nt]);
                }
        }
        __syncthreads();
    }

    const float sc = 0.03125f;  // 1/sqrt(1024)
    #pragma unroll
    for (int mt = 0; mt < MT; mt++)
        #pragma unroll
        for (int nt = 0; nt < NT; nt++) {
            int r = i0 + wm0 + mt * 16 + gid;
            int c = j0 + wn0 + nt * 8 + 2 * tig;
            float2 v0 = make_float2(sc * acc[mt][nt][0], sc * acc[mt][nt][1]);
            float2 v1 = make_float2(sc * acc[mt][nt][2], sc * acc[mt][nt][3]);
            *(float2*)(S + ((long long)h * SEQ + r) * SEQ + c) = v0;
            *(float2*)(S + ((long long)h * SEQ + r + 8) * SEQ + c) = v1;
        }
}

// ---------------------------------------------------------------------------
// Fused depthwise conv1d for q,k,v (k=3, same padding). blockIdx.y = tensor.
// ---------------------------------------------------------------------------
__global__ __launch_bounds__(256) void dwconv3(
    const float* __restrict__ q0, const float* __restrict__ k0, const float* __restrict__ v0,
    const float* __restrict__ cw,
    float* __restrict__ qc, float* __restrict__ kc, float* __restrict__ vc)
{
    const int z = blockIdx.y;
    const float* X = (z == 0) ? q0 : (z == 1) ? k0 : v0;
    float*       Y = (z == 0) ? qc : (z == 1) ? kc : vc;
    int idx = blockIdx.x * 256 + threadIdx.x;
    if (idx >= SEQ * CH) return;
    int c = idx & (CH - 1);
    int w = idx >> 10;
    float w0 = cw[c * 3 + 0], w1 = cw[c * 3 + 1], w2 = cw[c * 3 + 2];
    float acc = X[idx] * w1;
    if (w > 0)       acc += X[idx - CH] * w0;
    if (w < SEQ - 1) acc += X[idx + CH] * w2;
    Y[idx] = acc;
}

// ---------------------------------------------------------------------------
// Register-resident row softmax (row = 2048 floats, 256 threads)
// ---------------------------------------------------------------------------
__global__ __launch_bounds__(256) void softmax_rows(float* __restrict__ S)
{
    float* row = S + ((long long)blockIdx.y * SEQ + blockIdx.x) * SEQ;
    const int tid = threadIdx.x;
    __shared__ float red[8];

    float4 v[2];
    v[0] = ((float4*)row)[tid];
    v[1] = ((float4*)row)[tid + 256];

    float m = fmaxf(fmaxf(fmaxf(v[0].x, v[0].y), fmaxf(v[0].z, v[0].w)),
                    fmaxf(fmaxf(v[1].x, v[1].y), fmaxf(v[1].z, v[1].w)));
    #pragma unroll
    for (int s = 16; s > 0; s >>= 1) m = fmaxf(m, __shfl_xor_sync(~0u, m, s));
    if ((tid & 31) == 0) red[tid >> 5] = m;
    __syncthreads();
    m = red[0];
    #pragma unroll
    for (int i = 1; i < 8; i++) m = fmaxf(m, red[i]);
    __syncthreads();

    float sum = 0.f;
    #pragma unroll
    for (int i = 0; i < 2; i++) {
        v[i].x = __expf(v[i].x - m); sum += v[i].x;
        v[i].y = __expf(v[i].y - m); sum += v[i].y;
        v[i].z = __expf(v[i].z - m); sum += v[i].z;
        v[i].w = __expf(v[i].w - m); sum += v[i].w;
    }
    #pragma unroll
    for (int s = 16; s > 0; s >>= 1) sum += __shfl_xor_sync(~0u, sum, s);
    if ((tid & 31) == 0) red[tid >> 5] = sum;
    __syncthreads();
    sum = 0.f;
    #pragma unroll
    for (int i = 0; i < 8; i++) sum += red[i];
    float inv = 1.0f / sum;

    #pragma unroll
    for (int i = 0; i < 2; i++) {
        v[i].x *= inv; v[i].y *= inv; v[i].z *= inv; v[i].w *= inv;
    }
    ((float4*)row)[tid] = v[0];
    ((float4*)row)[tid + 256] = v[1];
}

// ---------------------------------------------------------------------------
// Launch
// ---------------------------------------------------------------------------
extern "C" void kernel_launch(void* const* d_in, const int* in_sizes, int n_in,
                              void* d_out, int out_size)
{
    const float* x  = (const float*)d_in[0];
    const float* wq = (const float*)d_in[1];
    const float* wk = (const float*)d_in[2];
    const float* wv = (const float*)d_in[3];
    const float* wo = (const float*)d_in[4];
    const float* cw = (const float*)d_in[5];
    const float* er = (const float*)d_in[6];
    float* out = (float*)d_out;

    float *q0, *k0, *v0, *qc, *kc, *vc, *S, *attn;
    cudaGetSymbolAddress((void**)&q0,   g_q0);
    cudaGetSymbolAddress((void**)&k0,   g_k0);
    cudaGetSymbolAddress((void**)&v0,   g_v0);
    cudaGetSymbolAddress((void**)&qc,   g_qc);
    cudaGetSymbolAddress((void**)&kc,   g_kc);
    cudaGetSymbolAddress((void**)&vc,   g_vc);
    cudaGetSymbolAddress((void**)&S,    g_S);
    cudaGetSymbolAddress((void**)&attn, g_attn);

    dim3 blk(256);

    // fused q/k/v projections (384 blocks)
    qkv_gemm<<<dim3(CH / 128, SEQ / 128, 3), blk>>>(x, wq, wk, wv, q0, k0, v0);

    // fused depthwise convs
    dwconv3<<<dim3(SEQ * CH / 256, 3), blk>>>(q0, k0, v0, cw, qc, kc, vc);

    // scores (+ relative-position term), softmax
    score_mma<<<dim3(SEQ / 128, SEQ / 128, NHEAD), blk>>>(qc, kc, er, S);
    softmax_rows<<<dim3(SEQ, NHEAD), blk>>>(S);

    // A @ V per head: M=2048, N=64, K=2048
    batch_gemm_av<<<dim3(1, SEQ / 128, NHEAD), blk>>>(
        S, vc, attn, SEQ, CH, CH, SEQ, 1.f,
        (long long)SEQ * SEQ, 64, 64);

    // output projection
    batch_gemm_128<<<dim3(CH / 128, SEQ / 128, 1), blk>>>(
        attn, wo, out, CH, CH, CH, CH, 1.f, 0, 0, 0);
}

// round 5
// speedup vs baseline: 3.1958x; 1.3667x over previous
#include <cuda_runtime.h>
#include <cstdint>

constexpr int SEQ   = 2048;
constexpr int CH    = 1024;
constexpr int NHEAD = 16;
constexpr int HDIM  = 64;

// ---------------------------------------------------------------------------
// Scratch (pre-split tf32 hi/lo pairs)
// ---------------------------------------------------------------------------
__device__ float g_xh[SEQ * CH],  g_xl[SEQ * CH];
__device__ float g_wh[4][CH * CH], g_wl[4][CH * CH];   // wq, wk, wv, wo
__device__ float g_erth[SEQ * HDIM], g_ertl[SEQ * HDIM];
__device__ float g_q0[SEQ * CH], g_k0[SEQ * CH], g_v0[SEQ * CH];
__device__ float g_qch[SEQ * CH], g_qcl[SEQ * CH];
__device__ float g_kch[SEQ * CH], g_kcl[SEQ * CH];
__device__ float g_vch[SEQ * CH], g_vcl[SEQ * CH];
__device__ float g_S [(long long)NHEAD * SEQ * SEQ];   // scores fp32, then probs hi
__device__ float g_Sl[(long long)NHEAD * SEQ * SEQ];   // probs lo
__device__ float g_ath[SEQ * CH], g_atl[SEQ * CH];

// ---------------------------------------------------------------------------
// Helpers
// ---------------------------------------------------------------------------
__device__ __forceinline__ uint32_t smem_u32(const void* p) {
    uint32_t a;
    asm("{ .reg .u64 t; cvta.to.shared.u64 t, %1; cvt.u32.u64 %0, t; }" : "=r"(a) : "l"(p));
    return a;
}
__device__ __forceinline__ void split_tf32(float x, float& hi, float& lo) {
    unsigned h;
    asm("cvt.rna.tf32.f32 %0, %1;" : "=r"(h) : "f"(x));
    hi = __uint_as_float(h);
    float r = x - hi;
    unsigned l;
    asm("cvt.rna.tf32.f32 %0, %1;" : "=r"(l) : "f"(r));
    lo = __uint_as_float(l);
}
__device__ __forceinline__ void mma_tf32(float* c, const uint32_t* a, const uint32_t* b) {
    asm volatile(
        "mma.sync.aligned.m16n8k8.row.col.f32.tf32.tf32.f32 "
        "{%0,%1,%2,%3},{%4,%5,%6,%7},{%8,%9},{%0,%1,%2,%3};"
        : "+f"(c[0]), "+f"(c[1]), "+f"(c[2]), "+f"(c[3])
        : "r"(a[0]), "r"(a[1]), "r"(a[2]), "r"(a[3]), "r"(b[0]), "r"(b[1]));
}
__device__ __forceinline__ void cpa16(uint32_t s, const void* g) {
    asm volatile("cp.async.ca.shared.global [%0], [%1], 16;" :: "r"(s), "l"(g));
}
__device__ __forceinline__ uint32_t lds32(uint32_t a) {
    uint32_t v;
    asm("ld.shared.b32 %0,[%1];" : "=r"(v) : "r"(a));
    return v;
}
#define CP_COMMIT() asm volatile("cp.async.commit_group;" ::: "memory")
#define CP_WAIT2()  asm volatile("cp.async.wait_group 2;" ::: "memory")

struct KtP { const float* ah; const float* al; const float* bh; const float* bl; int lda; int ldb; };

// ---------------------------------------------------------------------------
// 3-stage cp.async pipelined TF32x3 GEMM body.
// A smem: [row][k] stride 20 words.  B smem: BNK ? [n][k] stride 20
//                                            : [k][n] stride BN+8.
// C pointers pre-offset to block tile origin.
// ---------------------------------------------------------------------------
template<int BM, int BN, int WM, int WN, bool BNK, bool OSPL, typename F>
__device__ __forceinline__ void gemm_pipe(
    F&& ktf, int KT, float* C, float* Cl, int ldc, float alpha, char* sm_)
{
    constexpr int WARPS_M = BM / WM, WARPS_N = BN / WN;
    static_assert(WARPS_M * WARPS_N == 8, "");
    constexpr int MT = WM / 16, NT = WN / 8;
    constexpr int AW  = BM * 20;                       // words per A array (h or l)
    constexpr int BW_ = BNK ? BN * 20 : 16 * (BN + 8); // words per B array
    constexpr int STW = 2 * AW + 2 * BW_;
    constexpr int NSTG = 3;

    const uint32_t sb = smem_u32(sm_);
    const int tid = threadIdx.x, wid = tid >> 5, lane = tid & 31;
    const int gid = lane >> 2, tig = lane & 3;
    const int wm0 = (wid % WARPS_M) * WM, wn0 = (wid / WARPS_M) * WN;

    auto issue = [&](int s, int t) {
        KtP p = ktf(t);
        uint32_t st = sb + s * (STW * 4);
        #pragma unroll
        for (int i = 0; i < BM * 4 / 256; i++) {
            int id = tid + i * 256, row = id >> 2, kq = id & 3;
            uint32_t sa = st + (row * 20 + kq * 4) * 4;
            cpa16(sa,          p.ah + (long long)row * p.lda + kq * 4);
            cpa16(sa + AW * 4, p.al + (long long)row * p.lda + kq * 4);
        }
        if (BNK) {
            #pragma unroll
            for (int i = 0; i < BN * 4 / 256; i++) {
                int id = tid + i * 256, n = id >> 2, kq = id & 3;
                uint32_t sa = st + (2 * AW + n * 20 + kq * 4) * 4;
                cpa16(sa,           p.bh + (long long)n * p.ldb + kq * 4);
                cpa16(sa + BW_ * 4, p.bl + (long long)n * p.ldb + kq * 4);
            }
        } else {
            #pragma unroll
            for (int i = 0; i < 16 * (BN / 4) / 256; i++) {
                int id = tid + i * 256, k = id / (BN / 4), n4 = id % (BN / 4);
                uint32_t sa = st + (2 * AW + k * (BN + 8) + n4 * 4) * 4;
                cpa16(sa,           p.bh + (long long)k * p.ldb + n4 * 4);
                cpa16(sa + BW_ * 4, p.bl + (long long)k * p.ldb + n4 * 4);
            }
        }
    };

    float acc[MT][NT][4] = {};

    #pragma unroll
    for (int s = 0; s < NSTG; s++) {
        if (s < KT) issue(s, s);
        CP_COMMIT();
    }

    for (int t = 0; t < KT; t++) {
        int s = t % NSTG;
        CP_WAIT2();
        __syncthreads();

        uint32_t base = sb + s * (STW * 4);
        #pragma unroll
        for (int ks = 0; ks < 16; ks += 8) {
            uint32_t ah[MT][4], al[MT][4], bh[NT][2], bl[NT][2];
            #pragma unroll
            for (int mt = 0; mt < MT; mt++) {
                uint32_t r0 = base + ((wm0 + mt * 16 + gid) * 20 + ks + tig) * 4;
                ah[mt][0] = lds32(r0);
                ah[mt][1] = lds32(r0 + 8 * 20 * 4);
                ah[mt][2] = lds32(r0 + 16);
                ah[mt][3] = lds32(r0 + 8 * 20 * 4 + 16);
                uint32_t r1 = r0 + AW * 4;
                al[mt][0] = lds32(r1);
                al[mt][1] = lds32(r1 + 8 * 20 * 4);
                al[mt][2] = lds32(r1 + 16);
                al[mt][3] = lds32(r1 + 8 * 20 * 4 + 16);
            }
            #pragma unroll
            for (int nt = 0; nt < NT; nt++) {
                uint32_t b0;
                uint32_t stride4;
                if (BNK) {
                    b0 = base + (2 * AW + (wn0 + nt * 8 + gid) * 20 + ks + tig) * 4;
                    stride4 = 16;                       // k+4 -> +4 words
                } else {
                    b0 = base + (2 * AW + (ks + tig) * (BN + 8) + wn0 + nt * 8 + gid) * 4;
                    stride4 = 4 * (BN + 8) * 4;         // k+4 -> +4 rows
                }
                bh[nt][0] = lds32(b0);
                bh[nt][1] = lds32(b0 + stride4);
                uint32_t b1 = b0 + BW_ * 4;
                bl[nt][0] = lds32(b1);
                bl[nt][1] = lds32(b1 + stride4);
            }
            #pragma unroll
            for (int mt = 0; mt < MT; mt++)
                #pragma unroll
                for (int nt = 0; nt < NT; nt++) {
                    mma_tf32(acc[mt][nt], ah[mt], bh[nt]);
                    mma_tf32(acc[mt][nt], ah[mt], bl[nt]);
                    mma_tf32(acc[mt][nt], al[mt], bh[nt]);
                }
        }
        __syncthreads();
        if (t + NSTG < KT) issue(s, t + NSTG);
        CP_COMMIT();
    }

    #pragma unroll
    for (int mt = 0; mt < MT; mt++)
        #pragma unroll
        for (int nt = 0; nt < NT; nt++) {
            int r = wm0 + mt * 16 + gid;
            int c = wn0 + nt * 8 + 2 * tig;
            float v0 = alpha * acc[mt][nt][0], v1 = alpha * acc[mt][nt][1];
            float v2 = alpha * acc[mt][nt][2], v3 = alpha * acc[mt][nt][3];
            if (OSPL) {
                float h0, l0, h1, l1, h2, l2, h3, l3;
                split_tf32(v0, h0, l0); split_tf32(v1, h1, l1);
                split_tf32(v2, h2, l2); split_tf32(v3, h3, l3);
                *(float2*)(C  + (long long)r * ldc + c)       = make_float2(h0, h1);
                *(float2*)(Cl + (long long)r * ldc + c)       = make_float2(l0, l1);
                *(float2*)(C  + (long long)(r + 8) * ldc + c) = make_float2(h2, h3);
                *(float2*)(Cl + (long long)(r + 8) * ldc + c) = make_float2(l2, l3);
            } else {
                *(float2*)(C + (long long)r * ldc + c)       = make_float2(v0, v1);
                *(float2*)(C + (long long)(r + 8) * ldc + c) = make_float2(v2, v3);
            }
        }
}

// ---------------------------------------------------------------------------
// GEMM kernels
// ---------------------------------------------------------------------------
__global__ __launch_bounds__(256) void qkv_pipe(float* q0, float* k0, float* v0)
{
    extern __shared__ char smem[];
    const int z = blockIdx.z;
    const int m0 = blockIdx.y * 128, n0 = blockIdx.x * 128;
    const float* Ah = g_xh + (long long)m0 * CH;
    const float* Al = g_xl + (long long)m0 * CH;
    const float* Bh = g_wh[z] + n0;
    const float* Bl = g_wl[z] + n0;
    float* O = ((z == 0) ? q0 : (z == 1) ? k0 : v0) + (long long)m0 * CH + n0;
    auto ktf = [&](int t) -> KtP {
        return { Ah + t * 16, Al + t * 16,
                 Bh + (long long)t * 16 * CH, Bl + (long long)t * 16 * CH, CH, CH };
    };
    gemm_pipe<128, 128, 64, 32, false, false>(ktf, CH / 16, O, nullptr, CH, 1.f, smem);
}

__global__ __launch_bounds__(256) void wo_pipe(float* out)
{
    extern __shared__ char smem[];
    const int m0 = blockIdx.y * 128, n0 = blockIdx.x * 128;
    const float* Ah = g_ath + (long long)m0 * CH;
    const float* Al = g_atl + (long long)m0 * CH;
    const float* Bh = g_wh[3] + n0;
    const float* Bl = g_wl[3] + n0;
    float* O = out + (long long)m0 * CH + n0;
    auto ktf = [&](int t) -> KtP {
        return { Ah + t * 16, Al + t * 16,
                 Bh + (long long)t * 16 * CH, Bl + (long long)t * 16 * CH, CH, CH };
    };
    gemm_pipe<128, 128, 64, 32, false, false>(ktf, CH / 16, O, nullptr, CH, 1.f, smem);
}

// Score: S[h,i,j] = ( q_i.k_j + erT_i.q_j ) / 32 — virtual K = 128 (8 k-tiles)
__global__ __launch_bounds__(256) void score_pipe()
{
    extern __shared__ char smem[];
    const int h = blockIdx.z, cb = h * HDIM;
    const int i0 = blockIdx.y * 128, j0 = blockIdx.x * 128;
    float* O = g_S + ((long long)h * SEQ + i0) * SEQ + j0;
    auto ktf = [&](int t) -> KtP {
        if (t < 4)
            return { g_qch + (long long)i0 * CH + cb + t * 16,
                     g_qcl + (long long)i0 * CH + cb + t * 16,
                     g_kch + (long long)j0 * CH + cb + t * 16,
                     g_kcl + (long long)j0 * CH + cb + t * 16, CH, CH };
        int d0 = (t - 4) * 16;
        return { g_erth + (long long)i0 * HDIM + d0,
                 g_ertl + (long long)i0 * HDIM + d0,
                 g_qch + (long long)j0 * CH + cb + d0,
                 g_qcl + (long long)j0 * CH + cb + d0, HDIM, CH };
    };
    gemm_pipe<128, 128, 64, 32, true, false>(ktf, 8, O, nullptr, SEQ, 0.03125f, smem);
}

// A @ V per head: M=2048, N=64, K=2048 — split output for wo
__global__ __launch_bounds__(256) void av_pipe()
{
    extern __shared__ char smem[];
    const int h = blockIdx.z;
    const int m0 = blockIdx.y * 128;
    const float* Ah = g_S  + ((long long)h * SEQ + m0) * SEQ;
    const float* Al = g_Sl + ((long long)h * SEQ + m0) * SEQ;
    const float* Bh = g_vch + h * HDIM;
    const float* Bl = g_vcl + h * HDIM;
    float* Oh = g_ath + (long long)m0 * CH + h * HDIM;
    float* Ol = g_atl + (long long)m0 * CH + h * HDIM;
    auto ktf = [&](int t) -> KtP {
        return { Ah + t * 16, Al + t * 16,
                 Bh + (long long)t * 16 * CH, Bl + (long long)t * 16 * CH, SEQ, CH };
    };
    gemm_pipe<128, 64, 32, 32, false, true>(ktf, SEQ / 16, Oh, Ol, CH, 1.f, smem);
}

// ---------------------------------------------------------------------------
// Prep: split inputs to tf32 hi/lo; transpose-split er
// ---------------------------------------------------------------------------
__global__ __launch_bounds__(256) void split_arr(
    const float* __restrict__ in, float* __restrict__ oh, float* __restrict__ ol, int n)
{
    int i = blockIdx.x * 256 + threadIdx.x;
    if (i >= n) return;
    float h, l; split_tf32(in[i], h, l);
    oh[i] = h; ol[i] = l;
}
__global__ __launch_bounds__(256) void ert_split(const float* __restrict__ er)
{
    int idx = blockIdx.x * 256 + threadIdx.x;   // over SEQ*HDIM
    if (idx >= SEQ * HDIM) return;
    int i = idx >> 6, d = idx & 63;
    float h, l; split_tf32(er[(long long)d * SEQ + i], h, l);
    g_erth[idx] = h; g_ertl[idx] = l;
}

// ---------------------------------------------------------------------------
// Depthwise conv1d (k=3, same) fused q/k/v, split outputs
// ---------------------------------------------------------------------------
__global__ __launch_bounds__(256) void dwconv3(const float* __restrict__ cw)
{
    const int z = blockIdx.y;
    const float* X = (z == 0) ? g_q0 : (z == 1) ? g_k0 : g_v0;
    float* Yh = (z == 0) ? g_qch : (z == 1) ? g_kch : g_vch;
    float* Yl = (z == 0) ? g_qcl : (z == 1) ? g_kcl : g_vcl;
    int idx = blockIdx.x * 256 + threadIdx.x;
    if (idx >= SEQ * CH) return;
    int c = idx & (CH - 1);
    int w = idx >> 10;
    float w0 = cw[c * 3 + 0], w1 = cw[c * 3 + 1], w2 = cw[c * 3 + 2];
    float acc = X[idx] * w1;
    if (w > 0)       acc += X[idx - CH] * w0;
    if (w < SEQ - 1) acc += X[idx + CH] * w2;
    float h, l; split_tf32(acc, h, l);
    Yh[idx] = h; Yl[idx] = l;
}

// ---------------------------------------------------------------------------
// Softmax: read fp32 scores (g_S), write split probs (g_S hi, g_Sl lo)
// ---------------------------------------------------------------------------
__global__ __launch_bounds__(256) void softmax_rows()
{
    long long ro = ((long long)blockIdx.y * SEQ + blockIdx.x) * SEQ;
    float* row = g_S + ro;
    float* rol = g_Sl + ro;
    const int tid = threadIdx.x;
    __shared__ float red[8];

    float4 v[2];
    v[0] = ((float4*)row)[tid];
    v[1] = ((float4*)row)[tid + 256];

    float m = fmaxf(fmaxf(fmaxf(v[0].x, v[0].y), fmaxf(v[0].z, v[0].w)),
                    fmaxf(fmaxf(v[1].x, v[1].y), fmaxf(v[1].z, v[1].w)));
    #pragma unroll
    for (int s = 16; s > 0; s >>= 1) m = fmaxf(m, __shfl_xor_sync(~0u, m, s));
    if ((tid & 31) == 0) red[tid >> 5] = m;
    __syncthreads();
    m = red[0];
    #pragma unroll
    for (int i = 1; i < 8; i++) m = fmaxf(m, red[i]);
    __syncthreads();

    float sum = 0.f;
    #pragma unroll
    for (int i = 0; i < 2; i++) {
        v[i].x = __expf(v[i].x - m); sum += v[i].x;
        v[i].y = __expf(v[i].y - m); sum += v[i].y;
        v[i].z = __expf(v[i].z - m); sum += v[i].z;
        v[i].w = __expf(v[i].w - m); sum += v[i].w;
    }
    #pragma unroll
    for (int s = 16; s > 0; s >>= 1) sum += __shfl_xor_sync(~0u, sum, s);
    if ((tid & 31) == 0) red[tid >> 5] = sum;
    __syncthreads();
    sum = 0.f;
    #pragma unroll
    for (int i = 0; i < 8; i++) sum += red[i];
    float inv = 1.0f / sum;

    #pragma unroll
    for (int i = 0; i < 2; i++) {
        float4 hh, ll;
        split_tf32(v[i].x * inv, hh.x, ll.x);
        split_tf32(v[i].y * inv, hh.y, ll.y);
        split_tf32(v[i].z * inv, hh.z, ll.z);
        split_tf32(v[i].w * inv, hh.w, ll.w);
        ((float4*)row)[tid + i * 256] = hh;
        ((float4*)rol)[tid + i * 256] = ll;
    }
}

// ---------------------------------------------------------------------------
// Launch
// ---------------------------------------------------------------------------
extern "C" void kernel_launch(void* const* d_in, const int* in_sizes, int n_in,
                              void* d_out, int out_size)
{
    const float* x  = (const float*)d_in[0];
    const float* wq = (const float*)d_in[1];
    const float* wk = (const float*)d_in[2];
    const float* wv = (const float*)d_in[3];
    const float* wo = (const float*)d_in[4];
    const float* cw = (const float*)d_in[5];
    const float* er = (const float*)d_in[6];
    float* out = (float*)d_out;

    float *xh, *xl, *wh, *wl, *q0, *k0, *v0;
    cudaGetSymbolAddress((void**)&xh, g_xh);
    cudaGetSymbolAddress((void**)&xl, g_xl);
    cudaGetSymbolAddress((void**)&wh, g_wh);
    cudaGetSymbolAddress((void**)&wl, g_wl);
    cudaGetSymbolAddress((void**)&q0, g_q0);
    cudaGetSymbolAddress((void**)&k0, g_k0);
    cudaGetSymbolAddress((void**)&v0, g_v0);

    // smem sizes (3 stages)
    const int SM_QKV   = (2 * 128 * 20 + 2 * 16 * 136) * 4 * 3;   // 113,664
    const int SM_SCORE = (2 * 128 * 20 + 2 * 128 * 20) * 4 * 3;   // 122,880
    const int SM_AV    = (2 * 128 * 20 + 2 * 16 * 72) * 4 * 3;    //  89,088
    cudaFuncSetAttribute(qkv_pipe,   cudaFuncAttributeMaxDynamicSharedMemorySize, SM_QKV);
    cudaFuncSetAttribute(wo_pipe,    cudaFuncAttributeMaxDynamicSharedMemorySize, SM_QKV);
    cudaFuncSetAttribute(score_pipe, cudaFuncAttributeMaxDynamicSharedMemorySize, SM_SCORE);
    cudaFuncSetAttribute(av_pipe,    cudaFuncAttributeMaxDynamicSharedMemorySize, SM_AV);

    dim3 blk(256);

    // prep: split inputs
    split_arr<<<SEQ * CH / 256, blk>>>(x, xh, xl, SEQ * CH);
    split_arr<<<CH * CH / 256, blk>>>(wq, wh + 0 * CH * CH, wl + 0 * CH * CH, CH * CH);
    split_arr<<<CH * CH / 256, blk>>>(wk, wh + 1 * CH * CH, wl + 1 * CH * CH, CH * CH);
    split_arr<<<CH * CH / 256, blk>>>(wv, wh + 2 * CH * CH, wl + 2 * CH * CH, CH * CH);
    split_arr<<<CH * CH / 256, blk>>>(wo, wh + 3 * CH * CH, wl + 3 * CH * CH, CH * CH);
    ert_split<<<SEQ * HDIM / 256, blk>>>(er);

    // q/k/v projections
    qkv_pipe<<<dim3(CH / 128, SEQ / 128, 3), blk, SM_QKV>>>(q0, k0, v0);

    // depthwise conv (reference applies q_conv to q, k AND v), split outputs
    dwconv3<<<dim3(SEQ * CH / 256, 3), blk>>>(cw);

    // scores + rel-pos, softmax (split outputs)
    score_pipe<<<dim3(SEQ / 128, SEQ / 128, NHEAD), blk, SM_SCORE>>>();
    softmax_rows<<<dim3(SEQ, NHEAD), blk>>>();

    // A @ V per head (split output)
    av_pipe<<<dim3(1, SEQ / 128, NHEAD), blk, SM_AV>>>();

    // output projection
    wo_pipe<<<dim3(CH / 128, SEQ / 128, 1), blk, SM_QKV>>>(out);
}

// round 6
// speedup vs baseline: 4.9160x; 1.5383x over previous
#include <cuda_runtime.h>
#include <cuda_fp16.h>
#include <cstdint>

constexpr int SEQ   = 2048;
constexpr int CH    = 1024;
constexpr int NHEAD = 16;
constexpr int HDIM  = 64;

// ---------------------------------------------------------------------------
// Scratch
// ---------------------------------------------------------------------------
__device__ __half g_xh[SEQ * CH],  g_xl[SEQ * CH];           // x split, [w][c]
__device__ __half g_wth[4][CH * CH], g_wtl[4][CH * CH];      // W^T split, [n][k]
__device__ __half g_erth[SEQ * HDIM], g_ertl[SEQ * HDIM];    // er^T split, [i][d]
__device__ float  g_q0[SEQ * CH], g_k0[SEQ * CH], g_v0[SEQ * CH];
__device__ __half g_qch[SEQ * CH], g_qcl[SEQ * CH];          // conv(q) split, [w][c]
__device__ __half g_kch[SEQ * CH], g_kcl[SEQ * CH];
__device__ float  g_vc[SEQ * CH];                            // conv(v) fp32
__device__ __half g_vth[CH * SEQ], g_vtl[CH * SEQ];          // conv(v)^T split, [c][w]
__device__ float  g_S [(long long)NHEAD * SEQ * SEQ];        // fp32 scores
__device__ __half g_Sh[(long long)NHEAD * SEQ * SEQ];        // probs split
__device__ __half g_Sl[(long long)NHEAD * SEQ * SEQ];
__device__ __half g_ath[SEQ * CH], g_atl[SEQ * CH];          // attn split, [w][c]

// ---------------------------------------------------------------------------
// Helpers
// ---------------------------------------------------------------------------
__device__ __forceinline__ uint32_t smem_u32(const void* p) {
    uint32_t a;
    asm("{ .reg .u64 t; cvta.to.shared.u64 t, %1; cvt.u32.u64 %0, t; }" : "=r"(a) : "l"(p));
    return a;
}
__device__ __forceinline__ void split_h(float x, __half& h, __half& l) {
    h = __float2half_rn(x);
    l = __float2half_rn(x - __half2float(h));
}
__device__ __forceinline__ void mma_f16(float* c, const uint32_t* a, const uint32_t* b) {
    asm volatile(
        "mma.sync.aligned.m16n8k16.row.col.f32.f16.f16.f32 "
        "{%0,%1,%2,%3},{%4,%5,%6,%7},{%8,%9},{%0,%1,%2,%3};"
        : "+f"(c[0]), "+f"(c[1]), "+f"(c[2]), "+f"(c[3])
        : "r"(a[0]), "r"(a[1]), "r"(a[2]), "r"(a[3]), "r"(b[0]), "r"(b[1]));
}
__device__ __forceinline__ void cpa16(uint32_t s, const void* g) {
    asm volatile("cp.async.ca.shared.global [%0], [%1], 16;" :: "r"(s), "l"(g));
}
__device__ __forceinline__ uint32_t lds32(uint32_t a) {
    uint32_t v;
    asm("ld.shared.b32 %0,[%1];" : "=r"(v) : "r"(a));
    return v;
}
#define CP_COMMIT() asm volatile("cp.async.commit_group;" ::: "memory")
#define CP_WAIT2()  asm volatile("cp.async.wait_group 2;" ::: "memory")

struct KtH { const __half* ah; const __half* al; const __half* bh; const __half* bl;
             int lda; int ldb; };

// ---------------------------------------------------------------------------
// 3-stage cp.async pipelined FP16x3 GEMM body (m16n8k16).
// A smem: [m][k] rows of 16 halfs, stride 48 B (24 halfs) -> conflict-free.
// B smem: [n][k] same layout. K-tile = 16.
// ---------------------------------------------------------------------------
template<int BM, int BN, int WM, int WN, bool OSPL, typename F>
__device__ __forceinline__ void gemm_pipe(
    F&& ktf, int KT, float* C, __half* Ch, __half* Cl, int ldc, float alpha, char* sm_)
{
    constexpr int WARPS_M = BM / WM, WARPS_N = BN / WN;
    static_assert(WARPS_M * WARPS_N == 8, "");
    constexpr int MT = WM / 16, NT = WN / 8;
    constexpr int ABYT = BM * 48, BBYT = BN * 48;
    constexpr int STB  = 2 * ABYT + 2 * BBYT;
    constexpr int NSTG = 3;

    const uint32_t sb = smem_u32(sm_);
    const int tid = threadIdx.x, wid = tid >> 5, lane = tid & 31;
    const int gid = lane >> 2, tig = lane & 3;
    const int wm0 = (wid % WARPS_M) * WM, wn0 = (wid / WARPS_M) * WN;

    auto issue = [&](int s, int t) {
        KtH p = ktf(t);
        uint32_t st = sb + s * STB;
        #pragma unroll
        for (int i = 0; i < BM * 2 / 256; i++) {
            int id = tid + i * 256, row = id >> 1, c16 = id & 1;
            uint32_t sa = st + row * 48 + c16 * 16;
            cpa16(sa,        p.ah + (long long)row * p.lda + c16 * 8);
            cpa16(sa + ABYT, p.al + (long long)row * p.lda + c16 * 8);
        }
        #pragma unroll
        for (int i = 0; i < (BN * 2 + 255) / 256; i++) {
            int id = tid + i * 256;
            if (id < BN * 2) {
                int row = id >> 1, c16 = id & 1;
                uint32_t sa = st + 2 * ABYT + row * 48 + c16 * 16;
                cpa16(sa,        p.bh + (long long)row * p.ldb + c16 * 8);
                cpa16(sa + BBYT, p.bl + (long long)row * p.ldb + c16 * 8);
            }
        }
    };

    float acc[MT][NT][4] = {};

    #pragma unroll
    for (int s = 0; s < NSTG; s++) {
        if (s < KT) issue(s, s);
        CP_COMMIT();
    }

    for (int t = 0; t < KT; t++) {
        int s = t % NSTG;
        CP_WAIT2();
        __syncthreads();

        uint32_t base = sb + s * STB;
        uint32_t ah[MT][4], al[MT][4], bh[NT][2], bl[NT][2];
        #pragma unroll
        for (int mt = 0; mt < MT; mt++) {
            uint32_t a0 = base + (wm0 + mt * 16 + gid) * 48 + 4 * tig;
            ah[mt][0] = lds32(a0);
            ah[mt][1] = lds32(a0 + 8 * 48);
            ah[mt][2] = lds32(a0 + 16);
            ah[mt][3] = lds32(a0 + 8 * 48 + 16);
            uint32_t a1 = a0 + ABYT;
            al[mt][0] = lds32(a1);
            al[mt][1] = lds32(a1 + 8 * 48);
            al[mt][2] = lds32(a1 + 16);
            al[mt][3] = lds32(a1 + 8 * 48 + 16);
        }
        #pragma unroll
        for (int nt = 0; nt < NT; nt++) {
            uint32_t b0 = base + 2 * ABYT + (wn0 + nt * 8 + gid) * 48 + 4 * tig;
            bh[nt][0] = lds32(b0);
            bh[nt][1] = lds32(b0 + 16);
            uint32_t b1 = b0 + BBYT;
            bl[nt][0] = lds32(b1);
            bl[nt][1] = lds32(b1 + 16);
        }
        #pragma unroll
        for (int mt = 0; mt < MT; mt++)
            #pragma unroll
            for (int nt = 0; nt < NT; nt++) {
                mma_f16(acc[mt][nt], ah[mt], bh[nt]);
                mma_f16(acc[mt][nt], ah[mt], bl[nt]);
                mma_f16(acc[mt][nt], al[mt], bh[nt]);
            }
        __syncthreads();
        if (t + NSTG < KT) issue(s, t + NSTG);
        CP_COMMIT();
    }

    #pragma unroll
    for (int mt = 0; mt < MT; mt++)
        #pragma unroll
        for (int nt = 0; nt < NT; nt++) {
            int r = wm0 + mt * 16 + gid;
            int c = wn0 + nt * 8 + 2 * tig;
            #pragma unroll
            for (int half_ = 0; half_ < 2; half_++) {
                int rr = r + half_ * 8;
                float v0 = alpha * acc[mt][nt][half_ * 2 + 0];
                float v1 = alpha * acc[mt][nt][half_ * 2 + 1];
                if (OSPL) {
                    __half h0, l0, h1, l1;
                    split_h(v0, h0, l0); split_h(v1, h1, l1);
                    *(__half2*)(Ch + (long long)rr * ldc + c) = __halves2half2(h0, h1);
                    *(__half2*)(Cl + (long long)rr * ldc + c) = __halves2half2(l0, l1);
                } else {
                    *(float2*)(C + (long long)rr * ldc + c) = make_float2(v0, v1);
                }
            }
        }
}

// ---------------------------------------------------------------------------
// GEMM kernels
// ---------------------------------------------------------------------------
__global__ __launch_bounds__(256, 2) void qkv_pipe()
{
    extern __shared__ char smem[];
    const int z = blockIdx.z;
    const int m0 = blockIdx.y * 128, n0 = blockIdx.x * 128;
    float* O = ((z == 0) ? g_q0 : (z == 1) ? g_k0 : g_v0) + (long long)m0 * CH + n0;
    const __half* Ah = g_xh + (long long)m0 * CH;
    const __half* Al = g_xl + (long long)m0 * CH;
    const __half* Bh = g_wth[z] + (long long)n0 * CH;
    const __half* Bl = g_wtl[z] + (long long)n0 * CH;
    auto ktf = [&](int t) -> KtH {
        return { Ah + t * 16, Al + t * 16, Bh + t * 16, Bl + t * 16, CH, CH };
    };
    gemm_pipe<128, 128, 64, 32, false>(ktf, CH / 16, O, nullptr, nullptr, CH, 1.f, smem);
}

__global__ __launch_bounds__(256, 2) void wo_pipe(float* __restrict__ out)
{
    extern __shared__ char smem[];
    const int m0 = blockIdx.y * 128, n0 = blockIdx.x * 128;
    const __half* Ah = g_ath + (long long)m0 * CH;
    const __half* Al = g_atl + (long long)m0 * CH;
    const __half* Bh = g_wth[3] + (long long)n0 * CH;
    const __half* Bl = g_wtl[3] + (long long)n0 * CH;
    float* O = out + (long long)m0 * CH + n0;
    auto ktf = [&](int t) -> KtH {
        return { Ah + t * 16, Al + t * 16, Bh + t * 16, Bl + t * 16, CH, CH };
    };
    gemm_pipe<128, 128, 64, 32, false>(ktf, CH / 16, O, nullptr, nullptr, CH, 1.f, smem);
}

// Score: S[h,i,j] = ( q_i.k_j + erT_i.q_j ) / 32 — virtual K = 128 (8 k-tiles)
__global__ __launch_bounds__(256, 2) void score_pipe()
{
    extern __shared__ char smem[];
    const int h = blockIdx.z, cb = h * HDIM;
    const int i0 = blockIdx.y * 128, j0 = blockIdx.x * 128;
    float* O = g_S + ((long long)h * SEQ + i0) * SEQ + j0;
    auto ktf = [&](int t) -> KtH {
        if (t < 4)
            return { g_qch + (long long)i0 * CH + cb + t * 16,
                     g_qcl + (long long)i0 * CH + cb + t * 16,
                     g_kch + (long long)j0 * CH + cb + t * 16,
                     g_kcl + (long long)j0 * CH + cb + t * 16, CH, CH };
        int d0 = (t - 4) * 16;
        return { g_erth + (long long)i0 * HDIM + d0,
                 g_ertl + (long long)i0 * HDIM + d0,
                 g_qch + (long long)j0 * CH + cb + d0,
                 g_qcl + (long long)j0 * CH + cb + d0, HDIM, CH };
    };
    gemm_pipe<128, 128, 64, 32, false>(ktf, 8, O, nullptr, nullptr, SEQ, 0.03125f, smem);
}

// A @ V per head: M=2048, N=64, K=2048, split half output
__global__ __launch_bounds__(256, 2) void av_pipe()
{
    extern __shared__ char smem[];
    const int h = blockIdx.z;
    const int m0 = blockIdx.y * 128;
    const __half* Ah = g_Sh + ((long long)h * SEQ + m0) * SEQ;
    const __half* Al = g_Sl + ((long long)h * SEQ + m0) * SEQ;
    const __half* Bh = g_vth + (long long)(h * HDIM) * SEQ;
    const __half* Bl = g_vtl + (long long)(h * HDIM) * SEQ;
    __half* Oh = g_ath + (long long)m0 * CH + h * HDIM;
    __half* Ol = g_atl + (long long)m0 * CH + h * HDIM;
    auto ktf = [&](int t) -> KtH {
        return { Ah + t * 16, Al + t * 16, Bh + t * 16, Bl + t * 16, SEQ, SEQ };
    };
    gemm_pipe<128, 64, 32, 32, true>(ktf, SEQ / 16, nullptr, Oh, Ol, CH, 1.f, smem);
}

// ---------------------------------------------------------------------------
// Prep kernels
// ---------------------------------------------------------------------------
__global__ __launch_bounds__(256) void split_x(const float* __restrict__ x)
{
    int i = blockIdx.x * 256 + threadIdx.x;
    if (i >= SEQ * CH) return;
    __half h, l; split_h(x[i], h, l);
    g_xh[i] = h; g_xl[i] = l;
}

// in[R][C] fp32 -> out[C][R] split halves (tiled, coalesced both sides)
__global__ void transpose_split(const float* __restrict__ in,
                                __half* __restrict__ oh, __half* __restrict__ ol,
                                int R, int C)
{
    __shared__ float t[32][33];
    int c0 = blockIdx.x * 32, r0 = blockIdx.y * 32;
    int tx = threadIdx.x, ty = threadIdx.y;   // 32 x 8
    #pragma unroll
    for (int j = 0; j < 4; j++)
        t[ty + 8 * j][tx] = in[(long long)(r0 + ty + 8 * j) * C + c0 + tx];
    __syncthreads();
    #pragma unroll
    for (int j = 0; j < 4; j++) {
        float v = t[tx][ty + 8 * j];
        __half h, l; split_h(v, h, l);
        long long o = (long long)(c0 + ty + 8 * j) * R + r0 + tx;
        oh[o] = h; ol[o] = l;
    }
}

// ---------------------------------------------------------------------------
// Depthwise conv1d (k=3, same): q,k -> split halves; v -> fp32 (transposed later)
// ---------------------------------------------------------------------------
__global__ __launch_bounds__(256) void dwconv3(const float* __restrict__ cw)
{
    const int z = blockIdx.y;
    const float* X = (z == 0) ? g_q0 : (z == 1) ? g_k0 : g_v0;
    int idx = blockIdx.x * 256 + threadIdx.x;
    if (idx >= SEQ * CH) return;
    int c = idx & (CH - 1);
    int w = idx >> 10;
    float w0 = cw[c * 3 + 0], w1 = cw[c * 3 + 1], w2 = cw[c * 3 + 2];
    float acc = X[idx] * w1;
    if (w > 0)       acc += X[idx - CH] * w0;
    if (w < SEQ - 1) acc += X[idx + CH] * w2;
    if (z == 2) { g_vc[idx] = acc; return; }
    __half h, l; split_h(acc, h, l);
    if (z == 0) { g_qch[idx] = h; g_qcl[idx] = l; }
    else        { g_kch[idx] = h; g_kcl[idx] = l; }
}

// ---------------------------------------------------------------------------
// Softmax: fp32 scores -> split half probs
// ---------------------------------------------------------------------------
__global__ __launch_bounds__(256) void softmax_rows()
{
    long long ro = ((long long)blockIdx.y * SEQ + blockIdx.x) * SEQ;
    float* row = g_S + ro;
    __half2* rh = (__half2*)(g_Sh + ro);
    __half2* rl = (__half2*)(g_Sl + ro);
    const int tid = threadIdx.x;
    __shared__ float red[8];

    float4 v[2];
    v[0] = ((float4*)row)[tid];
    v[1] = ((float4*)row)[tid + 256];

    float m = fmaxf(fmaxf(fmaxf(v[0].x, v[0].y), fmaxf(v[0].z, v[0].w)),
                    fmaxf(fmaxf(v[1].x, v[1].y), fmaxf(v[1].z, v[1].w)));
    #pragma unroll
    for (int s = 16; s > 0; s >>= 1) m = fmaxf(m, __shfl_xor_sync(~0u, m, s));
    if ((tid & 31) == 0) red[tid >> 5] = m;
    __syncthreads();
    m = red[0];
    #pragma unroll
    for (int i = 1; i < 8; i++) m = fmaxf(m, red[i]);
    __syncthreads();

    float sum = 0.f;
    #pragma unroll
    for (int i = 0; i < 2; i++) {
        v[i].x = __expf(v[i].x - m); sum += v[i].x;
        v[i].y = __expf(v[i].y - m); sum += v[i].y;
        v[i].z = __expf(v[i].z - m); sum += v[i].z;
        v[i].w = __expf(v[i].w - m); sum += v[i].w;
    }
    #pragma unroll
    for (int s = 16; s > 0; s >>= 1) sum += __shfl_xor_sync(~0u, sum, s);
    if ((tid & 31) == 0) red[tid >> 5] = sum;
    __syncthreads();
    sum = 0.f;
    #pragma unroll
    for (int i = 0; i < 8; i++) sum += red[i];
    float inv = 1.0f / sum;

    #pragma unroll
    for (int i = 0; i < 2; i++) {
        float p0 = v[i].x * inv, p1 = v[i].y * inv, p2 = v[i].z * inv, p3 = v[i].w * inv;
        __half h0, l0, h1, l1, h2, l2, h3, l3;
        split_h(p0, h0, l0); split_h(p1, h1, l1);
        split_h(p2, h2, l2); split_h(p3, h3, l3);
        rh[(tid + i * 256) * 2 + 0] = __halves2half2(h0, h1);
        rh[(tid + i * 256) * 2 + 1] = __halves2half2(h2, h3);
        rl[(tid + i * 256) * 2 + 0] = __halves2half2(l0, l1);
        rl[(tid + i * 256) * 2 + 1] = __halves2half2(l2, l3);
    }
}

// ---------------------------------------------------------------------------
// Launch
// ---------------------------------------------------------------------------
extern "C" void kernel_launch(void* const* d_in, const int* in_sizes, int n_in,
                              void* d_out, int out_size)
{
    const float* x  = (const float*)d_in[0];
    const float* wq = (const float*)d_in[1];
    const float* wk = (const float*)d_in[2];
    const float* wv = (const float*)d_in[3];
    const float* wo = (const float*)d_in[4];
    const float* cw = (const float*)d_in[5];
    const float* er = (const float*)d_in[6];
    float* out = (float*)d_out;

    __half *wth, *wtl, *erth, *ertl, *vth, *vtl;
    float* vc;
    cudaGetSymbolAddress((void**)&wth,  g_wth);
    cudaGetSymbolAddress((void**)&wtl,  g_wtl);
    cudaGetSymbolAddress((void**)&erth, g_erth);
    cudaGetSymbolAddress((void**)&ertl, g_ertl);
    cudaGetSymbolAddress((void**)&vth,  g_vth);
    cudaGetSymbolAddress((void**)&vtl,  g_vtl);
    cudaGetSymbolAddress((void**)&vc,   g_vc);

    const int SM128 = (2 * 128 * 48 + 2 * 128 * 48) * 3;   // 73,728
    const int SM64  = (2 * 128 * 48 + 2 * 64 * 48) * 3;    // 55,296
    cudaFuncSetAttribute(qkv_pipe,   cudaFuncAttributeMaxDynamicSharedMemorySize, SM128);
    cudaFuncSetAttribute(wo_pipe,    cudaFuncAttributeMaxDynamicSharedMemorySize, SM128);
    cudaFuncSetAttribute(score_pipe, cudaFuncAttributeMaxDynamicSharedMemorySize, SM128);
    cudaFuncSetAttribute(av_pipe,    cudaFuncAttributeMaxDynamicSharedMemorySize, SM64);

    dim3 blk(256);
    dim3 tblk(32, 8);

    // prep: split x; transpose-split weights + er
    split_x<<<SEQ * CH / 256, blk>>>(x);
    const float* ws[4] = {wq, wk, wv, wo};
    for (int z = 0; z < 4; z++)
        transpose_split<<<dim3(32, 32), tblk>>>(ws[z], wth + (long long)z * CH * CH,
                                                wtl + (long long)z * CH * CH, CH, CH);
    transpose_split<<<dim3(64, 2), tblk>>>(er, erth, ertl, HDIM, SEQ);

    // q/k/v projections
    qkv_pipe<<<dim3(CH / 128, SEQ / 128, 3), blk, SM128>>>();

    // depthwise conv (reference applies q_conv to q, k AND v)
    dwconv3<<<dim3(SEQ * CH / 256, 3), blk>>>(cw);
    // transpose-split conv(v): [w][c] -> [c][w]
    transpose_split<<<dim3(32, 64), tblk>>>(vc, vth, vtl, SEQ, CH);

    // scores + rel-pos, softmax
    score_pipe<<<dim3(SEQ / 128, SEQ / 128, NHEAD), blk, SM128>>>();
    softmax_rows<<<dim3(SEQ, NHEAD), blk>>>();

    // A @ V per head
    av_pipe<<<dim3(1, SEQ / 128, NHEAD), blk, SM64>>>();

    // output projection
    wo_pipe<<<dim3(CH / 128, SEQ / 128, 1), blk, SM128>>>(out);
}

// round 7
// speedup vs baseline: 5.4057x; 1.0996x over previous
#include <cuda_runtime.h>
#include <cuda_fp16.h>
#include <cstdint>

constexpr int SEQ   = 2048;
constexpr int CH    = 1024;
constexpr int NHEAD = 16;
constexpr int HDIM  = 64;

// ---------------------------------------------------------------------------
// Scratch
// ---------------------------------------------------------------------------
__device__ __half g_xh[SEQ * CH],  g_xl[SEQ * CH];           // x split, [w][c]
__device__ __half g_wth[4][CH * CH], g_wtl[4][CH * CH];      // W^T split, [n][k]
__device__ __half g_erth[SEQ * HDIM], g_ertl[SEQ * HDIM];    // er^T split, [i][d]
__device__ float  g_q0[SEQ * CH], g_k0[SEQ * CH], g_v0[SEQ * CH];
__device__ __half g_qch[SEQ * CH], g_qcl[SEQ * CH];          // conv(q) split, [w][c]
__device__ __half g_kch[SEQ * CH], g_kcl[SEQ * CH];
__device__ float  g_vc[SEQ * CH];                            // conv(v) fp32
__device__ __half g_vth[CH * SEQ], g_vtl[CH * SEQ];          // conv(v)^T split, [c][w]
__device__ float  g_S [(long long)NHEAD * SEQ * SEQ];        // fp32 scores
__device__ __half g_Sh[(long long)NHEAD * SEQ * SEQ];        // probs split
__device__ __half g_Sl[(long long)NHEAD * SEQ * SEQ];
__device__ __half g_ath[SEQ * CH], g_atl[SEQ * CH];          // attn split, [w][c]

// ---------------------------------------------------------------------------
// Helpers
// ---------------------------------------------------------------------------
__device__ __forceinline__ uint32_t smem_u32(const void* p) {
    uint32_t a;
    asm("{ .reg .u64 t; cvta.to.shared.u64 t, %1; cvt.u32.u64 %0, t; }" : "=r"(a) : "l"(p));
    return a;
}
__device__ __forceinline__ void split_h(float x, __half& h, __half& l) {
    h = __float2half_rn(x);
    l = __float2half_rn(x - __half2float(h));
}
__device__ __forceinline__ void mma_f16(float* c, const uint32_t* a, const uint32_t* b) {
    asm volatile(
        "mma.sync.aligned.m16n8k16.row.col.f32.f16.f16.f32 "
        "{%0,%1,%2,%3},{%4,%5,%6,%7},{%8,%9},{%0,%1,%2,%3};"
        : "+f"(c[0]), "+f"(c[1]), "+f"(c[2]), "+f"(c[3])
        : "r"(a[0]), "r"(a[1]), "r"(a[2]), "r"(a[3]), "r"(b[0]), "r"(b[1]));
}
__device__ __forceinline__ void ldsm_x4(uint32_t* r, uint32_t addr) {
    asm volatile("ldmatrix.sync.aligned.m8n8.x4.shared.b16 {%0,%1,%2,%3}, [%4];"
        : "=r"(r[0]), "=r"(r[1]), "=r"(r[2]), "=r"(r[3]) : "r"(addr));
}
__device__ __forceinline__ void ldsm_x2(uint32_t* r, uint32_t addr) {
    asm volatile("ldmatrix.sync.aligned.m8n8.x2.shared.b16 {%0,%1}, [%2];"
        : "=r"(r[0]), "=r"(r[1]) : "r"(addr));
}
__device__ __forceinline__ void cpa16(uint32_t s, const void* g) {
    asm volatile("cp.async.ca.shared.global [%0], [%1], 16;" :: "r"(s), "l"(g));
}
#define CP_COMMIT() asm volatile("cp.async.commit_group;" ::: "memory")
#define CP_WAIT2()  asm volatile("cp.async.wait_group 2;" ::: "memory")

struct KtH { const __half* ah; const __half* al; const __half* bh; const __half* bl;
             int lda; int ldb; };

// ---------------------------------------------------------------------------
// 3-stage cp.async pipelined FP16x3 GEMM body (m16n8k16), ldmatrix fragments.
// A smem: [m][k] rows of 16 halfs, stride 48 B (conflict-free under LDSM).
// B smem: [n][k] same layout. K-tile = 16.
// ---------------------------------------------------------------------------
template<int BM, int BN, int WM, int WN, bool OSPL, typename F>
__device__ __forceinline__ void gemm_pipe(
    F&& ktf, int KT, float* C, __half* Ch, __half* Cl, int ldc, float alpha, char* sm_)
{
    constexpr int WARPS_M = BM / WM, WARPS_N = BN / WN;
    static_assert(WARPS_M * WARPS_N == 8, "");
    constexpr int MT = WM / 16, NT = WN / 8;
    constexpr int ABYT = BM * 48, BBYT = BN * 48;
    constexpr int STB  = 2 * ABYT + 2 * BBYT;
    constexpr int NSTG = 3;

    const uint32_t sb = smem_u32(sm_);
    const int tid = threadIdx.x, wid = tid >> 5, lane = tid & 31;
    const int gid = lane >> 2, tig = lane & 3;
    const int wm0 = (wid % WARPS_M) * WM, wn0 = (wid / WARPS_M) * WN;

    auto issue = [&](int s, int t) {
        KtH p = ktf(t);
        uint32_t st = sb + s * STB;
        #pragma unroll
        for (int i = 0; i < BM * 2 / 256; i++) {
            int id = tid + i * 256, row = id >> 1, c16 = id & 1;
            uint32_t sa = st + row * 48 + c16 * 16;
            cpa16(sa,        p.ah + (long long)row * p.lda + c16 * 8);
            cpa16(sa + ABYT, p.al + (long long)row * p.lda + c16 * 8);
        }
        #pragma unroll
        for (int i = 0; i < (BN * 2 + 255) / 256; i++) {
            int id = tid + i * 256;
            if (id < BN * 2) {
                int row = id >> 1, c16 = id & 1;
                uint32_t sa = st + 2 * ABYT + row * 48 + c16 * 16;
                cpa16(sa,        p.bh + (long long)row * p.ldb + c16 * 8);
                cpa16(sa + BBYT, p.bl + (long long)row * p.ldb + c16 * 8);
            }
        }
    };

    float acc[MT][NT][4] = {};

    #pragma unroll
    for (int s = 0; s < NSTG; s++) {
        if (s < KT) issue(s, s);
        CP_COMMIT();
    }

    for (int t = 0; t < KT; t++) {
        int s = t % NSTG;
        CP_WAIT2();
        __syncthreads();

        uint32_t base = sb + s * STB;
        uint32_t ah[MT][4], al[MT][4], bh[NT][2], bl[NT][2];
        #pragma unroll
        for (int mt = 0; mt < MT; mt++) {
            uint32_t a0 = base + (wm0 + mt * 16 + (lane & 15)) * 48 + (lane >> 4) * 16;
            ldsm_x4(ah[mt], a0);
            ldsm_x4(al[mt], a0 + ABYT);
        }
        #pragma unroll
        for (int nt = 0; nt < NT; nt++) {
            uint32_t b0 = base + 2 * ABYT + (wn0 + nt * 8 + (lane & 7)) * 48
                        + ((lane >> 3) & 1) * 16;
            ldsm_x2(bh[nt], b0);
            ldsm_x2(bl[nt], b0 + BBYT);
        }
        #pragma unroll
        for (int mt = 0; mt < MT; mt++)
            #pragma unroll
            for (int nt = 0; nt < NT; nt++) {
                mma_f16(acc[mt][nt], ah[mt], bh[nt]);
                mma_f16(acc[mt][nt], ah[mt], bl[nt]);
                mma_f16(acc[mt][nt], al[mt], bh[nt]);
            }
        __syncthreads();
        if (t + NSTG < KT) issue(s, t + NSTG);
        CP_COMMIT();
    }

    #pragma unroll
    for (int mt = 0; mt < MT; mt++)
        #pragma unroll
        for (int nt = 0; nt < NT; nt++) {
            int r = wm0 + mt * 16 + gid;
            int c = wn0 + nt * 8 + 2 * tig;
            #pragma unroll
            for (int half_ = 0; half_ < 2; half_++) {
                int rr = r + half_ * 8;
                float v0 = alpha * acc[mt][nt][half_ * 2 + 0];
                float v1 = alpha * acc[mt][nt][half_ * 2 + 1];
                if (OSPL) {
                    __half h0, l0, h1, l1;
                    split_h(v0, h0, l0); split_h(v1, h1, l1);
                    *(__half2*)(Ch + (long long)rr * ldc + c) = __halves2half2(h0, h1);
                    *(__half2*)(Cl + (long long)rr * ldc + c) = __halves2half2(l0, l1);
                } else {
                    *(float2*)(C + (long long)rr * ldc + c) = make_float2(v0, v1);
                }
            }
        }
}

// ---------------------------------------------------------------------------
// GEMM kernels
// ---------------------------------------------------------------------------
__global__ __launch_bounds__(256, 2) void qkv_pipe()
{
    extern __shared__ char smem[];
    const int z = blockIdx.z;
    const int m0 = blockIdx.y * 128, n0 = blockIdx.x * 128;
    float* O = ((z == 0) ? g_q0 : (z == 1) ? g_k0 : g_v0) + (long long)m0 * CH + n0;
    const __half* Ah = g_xh + (long long)m0 * CH;
    const __half* Al = g_xl + (long long)m0 * CH;
    const __half* Bh = g_wth[z] + (long long)n0 * CH;
    const __half* Bl = g_wtl[z] + (long long)n0 * CH;
    auto ktf = [&](int t) -> KtH {
        return { Ah + t * 16, Al + t * 16, Bh + t * 16, Bl + t * 16, CH, CH };
    };
    gemm_pipe<128, 128, 64, 32, false>(ktf, CH / 16, O, nullptr, nullptr, CH, 1.f, smem);
}

__global__ __launch_bounds__(256, 2) void wo_pipe(float* __restrict__ out)
{
    extern __shared__ char smem[];
    const int m0 = blockIdx.y * 128, n0 = blockIdx.x * 128;
    const __half* Ah = g_ath + (long long)m0 * CH;
    const __half* Al = g_atl + (long long)m0 * CH;
    const __half* Bh = g_wth[3] + (long long)n0 * CH;
    const __half* Bl = g_wtl[3] + (long long)n0 * CH;
    float* O = out + (long long)m0 * CH + n0;
    auto ktf = [&](int t) -> KtH {
        return { Ah + t * 16, Al + t * 16, Bh + t * 16, Bl + t * 16, CH, CH };
    };
    gemm_pipe<128, 128, 64, 32, false>(ktf, CH / 16, O, nullptr, nullptr, CH, 1.f, smem);
}

// Score: S[h,i,j] = ( q_i.k_j + erT_i.q_j ) / 32 — virtual K = 128 (8 k-tiles)
__global__ __launch_bounds__(256, 2) void score_pipe()
{
    extern __shared__ char smem[];
    const int h = blockIdx.z, cb = h * HDIM;
    const int i0 = blockIdx.y * 128, j0 = blockIdx.x * 128;
    float* O = g_S + ((long long)h * SEQ + i0) * SEQ + j0;
    auto ktf = [&](int t) -> KtH {
        if (t < 4)
            return { g_qch + (long long)i0 * CH + cb + t * 16,
                     g_qcl + (long long)i0 * CH + cb + t * 16,
                     g_kch + (long long)j0 * CH + cb + t * 16,
                     g_kcl + (long long)j0 * CH + cb + t * 16, CH, CH };
        int d0 = (t - 4) * 16;
        return { g_erth + (long long)i0 * HDIM + d0,
                 g_ertl + (long long)i0 * HDIM + d0,
                 g_qch + (long long)j0 * CH + cb + d0,
                 g_qcl + (long long)j0 * CH + cb + d0, HDIM, CH };
    };
    gemm_pipe<128, 128, 64, 32, false>(ktf, 8, O, nullptr, nullptr, SEQ, 0.03125f, smem);
}

// A @ V per head: M=2048, N=64, K=2048, split half output
__global__ __launch_bounds__(256, 2) void av_pipe()
{
    extern __shared__ char smem[];
    const int h = blockIdx.z;
    const int m0 = blockIdx.y * 128;
    const __half* Ah = g_Sh + ((long long)h * SEQ + m0) * SEQ;
    const __half* Al = g_Sl + ((long long)h * SEQ + m0) * SEQ;
    const __half* Bh = g_vth + (long long)(h * HDIM) * SEQ;
    const __half* Bl = g_vtl + (long long)(h * HDIM) * SEQ;
    __half* Oh = g_ath + (long long)m0 * CH + h * HDIM;
    __half* Ol = g_atl + (long long)m0 * CH + h * HDIM;
    auto ktf = [&](int t) -> KtH {
        return { Ah + t * 16, Al + t * 16, Bh + t * 16, Bl + t * 16, SEQ, SEQ };
    };
    gemm_pipe<128, 64, 32, 32, true>(ktf, SEQ / 16, nullptr, Oh, Ol, CH, 1.f, smem);
}

// ---------------------------------------------------------------------------
// Prep kernels
// ---------------------------------------------------------------------------
__global__ __launch_bounds__(256) void split_x(const float* __restrict__ x)
{
    int i = blockIdx.x * 256 + threadIdx.x;
    if (i >= SEQ * CH) return;
    __half h, l; split_h(x[i], h, l);
    g_xh[i] = h; g_xl[i] = l;
}

// in[R][C] fp32 -> out[C][R] split halves (tiled, coalesced both sides)
__global__ void transpose_split(const float* __restrict__ in,
                                __half* __restrict__ oh, __half* __restrict__ ol,
                                int R, int C)
{
    __shared__ float t[32][33];
    int c0 = blockIdx.x * 32, r0 = blockIdx.y * 32;
    int tx = threadIdx.x, ty = threadIdx.y;   // 32 x 8
    #pragma unroll
    for (int j = 0; j < 4; j++)
        t[ty + 8 * j][tx] = in[(long long)(r0 + ty + 8 * j) * C + c0 + tx];
    __syncthreads();
    #pragma unroll
    for (int j = 0; j < 4; j++) {
        float v = t[tx][ty + 8 * j];
        __half h, l; split_h(v, h, l);
        long long o = (long long)(c0 + ty + 8 * j) * R + r0 + tx;
        oh[o] = h; ol[o] = l;
    }
}

// ---------------------------------------------------------------------------
// Depthwise conv1d (k=3, same): q,k -> split halves; v -> fp32 (transposed later)
// ---------------------------------------------------------------------------
__global__ __launch_bounds__(256) void dwconv3(const float* __restrict__ cw)
{
    const int z = blockIdx.y;
    const float* X = (z == 0) ? g_q0 : (z == 1) ? g_k0 : g_v0;
    int idx = blockIdx.x * 256 + threadIdx.x;
    if (idx >= SEQ * CH) return;
    int c = idx & (CH - 1);
    int w = idx >> 10;
    float w0 = cw[c * 3 + 0], w1 = cw[c * 3 + 1], w2 = cw[c * 3 + 2];
    float acc = X[idx] * w1;
    if (w > 0)       acc += X[idx - CH] * w0;
    if (w < SEQ - 1) acc += X[idx + CH] * w2;
    if (z == 2) { g_vc[idx] = acc; return; }
    __half h, l; split_h(acc, h, l);
    if (z == 0) { g_qch[idx] = h; g_qcl[idx] = l; }
    else        { g_kch[idx] = h; g_kcl[idx] = l; }
}

// ---------------------------------------------------------------------------
// Softmax: fp32 scores -> split half probs
// ---------------------------------------------------------------------------
__global__ __launch_bounds__(256) void softmax_rows()
{
    long long ro = ((long long)blockIdx.y * SEQ + blockIdx.x) * SEQ;
    float* row = g_S + ro;
    __half2* rh = (__half2*)(g_Sh + ro);
    __half2* rl = (__half2*)(g_Sl + ro);
    const int tid = threadIdx.x;
    __shared__ float red[8];

    float4 v[2];
    v[0] = ((float4*)row)[tid];
    v[1] = ((float4*)row)[tid + 256];

    float m = fmaxf(fmaxf(fmaxf(v[0].x, v[0].y), fmaxf(v[0].z, v[0].w)),
                    fmaxf(fmaxf(v[1].x, v[1].y), fmaxf(v[1].z, v[1].w)));
    #pragma unroll
    for (int s = 16; s > 0; s >>= 1) m = fmaxf(m, __shfl_xor_sync(~0u, m, s));
    if ((tid & 31) == 0) red[tid >> 5] = m;
    __syncthreads();
    m = red[0];
    #pragma unroll
    for (int i = 1; i < 8; i++) m = fmaxf(m, red[i]);
    __syncthreads();

    float sum = 0.f;
    #pragma unroll
    for (int i = 0; i < 2; i++) {
        v[i].x = __expf(v[i].x - m); sum += v[i].x;
        v[i].y = __expf(v[i].y - m); sum += v[i].y;
        v[i].z = __expf(v[i].z - m); sum += v[i].z;
        v[i].w = __expf(v[i].w - m); sum += v[i].w;
    }
    #pragma unroll
    for (int s = 16; s > 0; s >>= 1) sum += __shfl_xor_sync(~0u, sum, s);
    if ((tid & 31) == 0) red[tid >> 5] = sum;
    __syncthreads();
    sum = 0.f;
    #pragma unroll
    for (int i = 0; i < 8; i++) sum += red[i];
    float inv = 1.0f / sum;

    #pragma unroll
    for (int i = 0; i < 2; i++) {
        float p0 = v[i].x * inv, p1 = v[i].y * inv, p2 = v[i].z * inv, p3 = v[i].w * inv;
        __half h0, l0, h1, l1, h2, l2, h3, l3;
        split_h(p0, h0, l0); split_h(p1, h1, l1);
        split_h(p2, h2, l2); split_h(p3, h3, l3);
        rh[(tid + i * 256) * 2 + 0] = __halves2half2(h0, h1);
        rh[(tid + i * 256) * 2 + 1] = __halves2half2(h2, h3);
        rl[(tid + i * 256) * 2 + 0] = __halves2half2(l0, l1);
        rl[(tid + i * 256) * 2 + 1] = __halves2half2(l2, l3);
    }
}

// ---------------------------------------------------------------------------
// Launch
// ---------------------------------------------------------------------------
extern "C" void kernel_launch(void* const* d_in, const int* in_sizes, int n_in,
                              void* d_out, int out_size)
{
    const float* x  = (const float*)d_in[0];
    const float* wq = (const float*)d_in[1];
    const float* wk = (const float*)d_in[2];
    const float* wv = (const float*)d_in[3];
    const float* wo = (const float*)d_in[4];
    const float* cw = (const float*)d_in[5];
    const float* er = (const float*)d_in[6];
    float* out = (float*)d_out;

    __half *wth, *wtl, *erth, *ertl, *vth, *vtl;
    float* vc;
    cudaGetSymbolAddress((void**)&wth,  g_wth);
    cudaGetSymbolAddress((void**)&wtl,  g_wtl);
    cudaGetSymbolAddress((void**)&erth, g_erth);
    cudaGetSymbolAddress((void**)&ertl, g_ertl);
    cudaGetSymbolAddress((void**)&vth,  g_vth);
    cudaGetSymbolAddress((void**)&vtl,  g_vtl);
    cudaGetSymbolAddress((void**)&vc,   g_vc);

    const int SM128 = (2 * 128 * 48 + 2 * 128 * 48) * 3;   // 73,728
    const int SM64  = (2 * 128 * 48 + 2 * 64 * 48) * 3;    // 55,296
    cudaFuncSetAttribute(qkv_pipe,   cudaFuncAttributeMaxDynamicSharedMemorySize, SM128);
    cudaFuncSetAttribute(wo_pipe,    cudaFuncAttributeMaxDynamicSharedMemorySize, SM128);
    cudaFuncSetAttribute(score_pipe, cudaFuncAttributeMaxDynamicSharedMemorySize, SM128);
    cudaFuncSetAttribute(av_pipe,    cudaFuncAttributeMaxDynamicSharedMemorySize, SM64);

    dim3 blk(256);
    dim3 tblk(32, 8);

    // prep: split x; transpose-split weights + er
    split_x<<<SEQ * CH / 256, blk>>>(x);
    const float* ws[4] = {wq, wk, wv, wo};
    for (int z = 0; z < 4; z++)
        transpose_split<<<dim3(32, 32), tblk>>>(ws[z], wth + (long long)z * CH * CH,
                                                wtl + (long long)z * CH * CH, CH, CH);
    transpose_split<<<dim3(64, 2), tblk>>>(er, erth, ertl, HDIM, SEQ);

    // q/k/v projections
    qkv_pipe<<<dim3(CH / 128, SEQ / 128, 3), blk, SM128>>>();

    // depthwise conv (reference applies q_conv to q, k AND v)
    dwconv3<<<dim3(SEQ * CH / 256, 3), blk>>>(cw);
    // transpose-split conv(v): [w][c] -> [c][w]
    transpose_split<<<dim3(32, 64), tblk>>>(vc, vth, vtl, SEQ, CH);

    // scores + rel-pos, softmax
    score_pipe<<<dim3(SEQ / 128, SEQ / 128, NHEAD), blk, SM128>>>();
    softmax_rows<<<dim3(SEQ, NHEAD), blk>>>();

    // A @ V per head
    av_pipe<<<dim3(1, SEQ / 128, NHEAD), blk, SM64>>>();

    // output projection
    wo_pipe<<<dim3(CH / 128, SEQ / 128, 1), blk, SM128>>>(out);
}